// round 2
// baseline (speedup 1.0000x reference)
#include <cuda_runtime.h>
#include <math.h>

#define Bn 8
#define Cn 128
#define Hn 224
#define Wn 224
#define HWn (Hn*Wn)        // 50176
#define CHWn (Cn*HWn)      // 6422528
#define NPIX (Bn*HWn)      // 401408

// ---------------- scratch (static device globals; no allocation) ----------------
__device__ float g_y[Bn*CHWn];        // post-branch+shuffle, pre-LN2 tensor (205.5 MB)
__device__ float g_m1[NPIX];
__device__ float g_r1[NPIX];
__device__ float g_m2[NPIX];
__device__ float g_r2[NPIX];

// ---------------- constant weights ----------------
__constant__ float c_n1w[Cn], c_n1b[Cn];
__constant__ float c_sdw_w[4][32][9];   // branch dw weights in group order (s2,s4,s1,s3)
__constant__ float c_sdw_b[4][32];
__constant__ float c_spw_w[4][32][32];  // [g][o][c]
__constant__ float c_spw_b[4][32];
__constant__ float c_c5w[Cn][9];
__constant__ float c_c5b[Cn];
__constant__ float c_n2w[Cn], c_n2b[Cn];
__constant__ float c_ldww[Cn][9];
__constant__ float c_ldwb[Cn];
__constant__ float c_lpwb[Cn];

__device__ __forceinline__ float gelu_exact(float x) {
    return 0.5f * x * (1.0f + erff(x * 0.70710678118654752f));
}

// ================= kernel 1: LN1 stats (mean, rstd per pixel) =================
__global__ __launch_bounds__(256) void k1_stats(const float* __restrict__ x)
{
    int idx = blockIdx.x * 256 + threadIdx.x;   // 0..NPIX-1, exact grid
    int b  = idx / HWn;
    int hw = idx - b * HWn;
    const float* px = x + b * CHWn + hw;
    float s = 0.f, ss = 0.f;
    #pragma unroll 8
    for (int ch = 0; ch < Cn; ch++) {
        float v = px[ch * HWn];
        s += v; ss = fmaf(v, v, ss);
    }
    float m = s * (1.0f/128.0f);
    float var = fmaf(-m, m, ss * (1.0f/128.0f));
    g_m1[idx] = m;
    g_r1[idx] = rsqrtf(var + 1e-6f);
}

// ================= kernel 2: branches + c5 + shuffle + LN2 stats =================
// tile 16x16 pixels, halo 2 (shift 1 + conv 1). 256 threads, 1 pixel/thread.
#define T2 16
#define R2 20      // T2 + 4
__global__ __launch_bounds__(256, 1) void k2_mix(const float* __restrict__ x)
{
    __shared__ float sstat[2][R2*R2];
    extern __shared__ float sx[];              // [128][R2*R2]  (204800 B)

    const int b  = blockIdx.z;
    const int h0 = blockIdx.y * T2;
    const int w0 = blockIdx.x * T2;
    const int tid = threadIdx.x;
    const int xb = b * CHWn;

    // stage LN1 stats for the halo region
    for (int i = tid; i < R2*R2; i += 256) {
        int r = i / R2, cc = i - r * R2;
        int gh = h0 + r - 2, gw = w0 + cc - 2;
        float m = 0.f, rs = 0.f;
        if ((unsigned)gh < (unsigned)Hn && (unsigned)gw < (unsigned)Wn) {
            int p = b * HWn + gh * Wn + gw;
            m = g_m1[p]; rs = g_r1[p];
        }
        sstat[0][i] = m; sstat[1][i] = rs;
    }
    __syncthreads();

    // stage LN1(x) tile with halo; zeros outside image (= conv/shift zero-fill post-LN)
    for (int i = tid; i < Cn * (R2*R2); i += 256) {
        int ch  = i / (R2*R2);
        int pos = i - ch * (R2*R2);
        int r = pos / R2, cc = pos - r * R2;
        int gh = h0 + r - 2, gw = w0 + cc - 2;
        float v = 0.f;
        if ((unsigned)gh < (unsigned)Hn && (unsigned)gw < (unsigned)Wn) {
            float xx = x[xb + ch * HWn + gh * Wn + gw];
            v = (xx - sstat[0][pos]) * sstat[1][pos] * c_n1w[ch] + c_n1b[ch];
        }
        sx[ch * (R2*R2) + pos] = v;
    }
    __syncthreads();

    const int ty = tid >> 4, tx = tid & 15;
    const int h = h0 + ty, w = w0 + tx;

    // conv-pad masks for shifted branches: tap position p+k-1 must be inside image
    bool my[3], mx[3];
    #pragma unroll
    for (int k = 0; k < 3; k++) {
        my[k] = (unsigned)(h + k - 1) < (unsigned)Hn;
        mx[k] = (unsigned)(w + k - 1) < (unsigned)Wn;
    }

    // group g -> source chunk base, shift (weights already packed per-g in constant)
    const int SRC[4] = {32, 96, 0, 64};     // x2, x4, x1, x3
    const int SHH[4] = {-1, 1, 1, -1};
    const int SHW[4] = { 1,-1, 1, -1};

    float sum2 = 0.f, sq2 = 0.f;

    #pragma unroll
    for (int g = 0; g < 4; g++) {
        float t[32];
        #pragma unroll
        for (int c = 0; c < 32; c++) {
            // base points at tap (ky=0,kx=0): global (h-1-shh, w-1-shw) -> smem (ty+1-shh, tx+1-shw)
            const float* bp = &sx[(SRC[g] + c) * (R2*R2) + (ty + 1 - SHH[g]) * R2 + (tx + 1 - SHW[g])];
            float a = c_sdw_b[g][c];
            #pragma unroll
            for (int ky = 0; ky < 3; ky++)
                #pragma unroll
                for (int kx = 0; kx < 3; kx++)
                    if (my[ky] && mx[kx])
                        a = fmaf(c_sdw_w[g][c][ky*3+kx], bp[ky*R2 + kx], a);
            t[c] = gelu_exact(a);
        }
        #pragma unroll
        for (int o = 0; o < 32; o++) {
            const int ci = g * 32 + o;          // pre-shuffle channel
            float v = c_spw_b[g][o];
            #pragma unroll
            for (int c = 0; c < 32; c++)
                v = fmaf(c_spw_w[g][o][c], t[c], v);
            // residual: dw3(c5) of LN1(x) channel ci (smem zeros give SAME padding)
            const float* b5 = &sx[ci * (R2*R2) + (ty + 1) * R2 + (tx + 1)];
            float a5 = c_c5b[ci];
            #pragma unroll
            for (int k = 0; k < 9; k++)
                a5 = fmaf(c_c5w[ci][k], b5[(k/3)*R2 + (k%3)], a5);
            v += a5;
            sum2 += v;
            sq2 = fmaf(v, v, sq2);
            // channel shuffle (2 groups): ci -> 2*(ci%64) + ci/64
            const int ko = ((ci & 63) << 1) | (ci >> 6);
            g_y[xb + ko * HWn + h * Wn + w] = v;
        }
    }

    float m2  = sum2 * (1.0f/128.0f);
    float var = fmaf(-m2, m2, sq2 * (1.0f/128.0f));
    int p = b * HWn + h * Wn + w;
    g_m2[p] = m2;
    g_r2[p] = rsqrtf(var + 1e-6f);
}

// ================= kernel 3: LN2(load) -> dw3 -> gelu -> pw 128x128 =================
// tile 8x8 px, halo 1; smem GEMM 128(o) x 64(px) x 128(c), 8o x 4px per thread.
#define T3 8
#define R3 10
#define WPAD 132
__global__ __launch_bounds__(256, 1) void k3_final(const float* __restrict__ pw,
                                                   float* __restrict__ out)
{
    extern __shared__ float sm3[];
    float* Wsm = sm3;                        // [128][WPAD]  transposed: Wsm[c][o]
    float* gsm = Wsm + Cn * WPAD;            // [128][64]
    float* ysm = gsm + Cn * 64;              // [128][R3*R3]

    const int b  = blockIdx.z;
    const int h0 = blockIdx.y * T3;
    const int w0 = blockIdx.x * T3;
    const int tid = threadIdx.x;
    const int xb = b * CHWn;

    // stage pw weights transposed
    for (int i = tid; i < Cn * Cn; i += 256) {
        int o = i >> 7, c = i & 127;
        Wsm[c * WPAD + o] = pw[i];
    }
    // stage LN2(y) tile with halo; zeros outside image
    for (int i = tid; i < Cn * (R3*R3); i += 256) {
        int ch  = i / (R3*R3);
        int pos = i - ch * (R3*R3);
        int r = pos / R3, cc = pos - r * R3;
        int gh = h0 + r - 1, gw = w0 + cc - 1;
        float v = 0.f;
        if ((unsigned)gh < (unsigned)Hn && (unsigned)gw < (unsigned)Wn) {
            int p = b * HWn + gh * Wn + gw;
            v = (g_y[xb + ch * HWn + gh * Wn + gw] - g_m2[p]) * g_r2[p] * c_n2w[ch] + c_n2b[ch];
        }
        ysm[ch * (R3*R3) + pos] = v;
    }
    __syncthreads();

    // g = gelu(dw3(yln))
    for (int i = tid; i < Cn * 64; i += 256) {
        int ch = i >> 6, p = i & 63;
        int py = p >> 3, px = p & 7;
        const float* bp = &ysm[ch * (R3*R3) + py * R3 + px];
        float a = c_ldwb[ch];
        #pragma unroll
        for (int k = 0; k < 9; k++)
            a = fmaf(c_ldww[ch][k], bp[(k/3)*R3 + (k%3)], a);
        gsm[ch * 64 + p] = gelu_exact(a);
    }
    __syncthreads();

    // register-blocked GEMM: out[o, p] = b[o] + sum_c W[o,c] * g[c,p]
    const int q  = (tid & 15) * 4;     // 4 consecutive pixels
    const int o0 = (tid >> 4) * 8;     // 8 output channels
    float acc[8][4];
    #pragma unroll
    for (int j = 0; j < 8; j++) {
        float bj = c_lpwb[o0 + j];
        acc[j][0] = bj; acc[j][1] = bj; acc[j][2] = bj; acc[j][3] = bj;
    }
    #pragma unroll 4
    for (int c = 0; c < Cn; c++) {
        const float4 gv = *reinterpret_cast<const float4*>(&gsm[c * 64 + q]);
        const float* wr = &Wsm[c * WPAD + o0];
        #pragma unroll
        for (int j = 0; j < 8; j++) {
            float wv = wr[j];
            acc[j][0] = fmaf(wv, gv.x, acc[j][0]);
            acc[j][1] = fmaf(wv, gv.y, acc[j][1]);
            acc[j][2] = fmaf(wv, gv.z, acc[j][2]);
            acc[j][3] = fmaf(wv, gv.w, acc[j][3]);
        }
    }
    #pragma unroll
    for (int j = 0; j < 8; j++)
        #pragma unroll
        for (int i = 0; i < 4; i++) {
            int p = q + i;
            out[xb + (o0 + j) * HWn + (h0 + (p >> 3)) * Wn + (w0 + (p & 7))] = acc[j][i];
        }
}

// ================= launch =================
extern "C" void kernel_launch(void* const* d_in, const int* in_sizes, int n_in,
                              void* d_out, int out_size)
{
    (void)out_size;
    // ---- resolve input indices by element count (order-agnostic) ----
    // classes: x=6422528, ldw_pw_w=16384, {c5_w, ldw_dw_w}=1152 (c5 first),
    //          s1..s4_dw_w=288 (in order), s1..s4_pw_w=1024 (in order),
    //          size-128: n1_w, n1_b first; n2_w, n2_b are the two remaining after
    //          excluding bias slots (each _b sits at its _w index + 1).
    int idx_x = 0, idx_lpw = -1, idx_c5w = -1, idx_ldww = -1;
    int dw_w[4] = {-1,-1,-1,-1}, pw_w[4] = {-1,-1,-1,-1};
    int ndw = 0, npw = 0;
    for (int i = 0; i < n_in; i++) {
        int s = in_sizes[i];
        if (s > 100000)      idx_x = i;
        else if (s == 16384) idx_lpw = i;
        else if (s == 1152)  { if (idx_c5w < 0) idx_c5w = i; else idx_ldww = i; }
        else if (s == 288 && ndw < 4)  dw_w[ndw++] = i;
        else if (s == 1024 && npw < 4) pw_w[npw++] = i;
    }
    const int idx_c5b  = idx_c5w  + 1;
    const int idx_ldwb = idx_ldww + 1;
    const int idx_lpwb = idx_lpw  + 1;
    // size-128 vectors that are NOT one of the bias slots above: n1_w, n1_b, n2_w, n2_b
    int v128[8]; int nv = 0;
    for (int i = 0; i < n_in; i++) {
        if (in_sizes[i] == 128 && i != idx_c5b && i != idx_ldwb && i != idx_lpwb && nv < 8)
            v128[nv++] = i;
    }
    const int idx_n1w = v128[0], idx_n1b = v128[1];
    const int idx_n2w = v128[2], idx_n2b = v128[3];

    const float* x = (const float*)d_in[idx_x];

    cudaMemcpyToSymbolAsync(c_n1w, d_in[idx_n1w], Cn*4, 0, cudaMemcpyDeviceToDevice);
    cudaMemcpyToSymbolAsync(c_n1b, d_in[idx_n1b], Cn*4, 0, cudaMemcpyDeviceToDevice);
    // group order g0..g3 = s2, s4, s1, s3
    const int GS[4] = {1, 3, 0, 2};
    for (int g = 0; g < 4; g++) {
        int sb = GS[g];
        cudaMemcpyToSymbolAsync(c_sdw_w, d_in[dw_w[sb]],     32*9*4,  g*32*9*4,  cudaMemcpyDeviceToDevice);
        cudaMemcpyToSymbolAsync(c_sdw_b, d_in[dw_w[sb] + 1], 32*4,    g*32*4,    cudaMemcpyDeviceToDevice);
        cudaMemcpyToSymbolAsync(c_spw_w, d_in[pw_w[sb]],     32*32*4, g*32*32*4, cudaMemcpyDeviceToDevice);
        cudaMemcpyToSymbolAsync(c_spw_b, d_in[pw_w[sb] + 1], 32*4,    g*32*4,    cudaMemcpyDeviceToDevice);
    }
    cudaMemcpyToSymbolAsync(c_c5w,  d_in[idx_c5w],  Cn*9*4, 0, cudaMemcpyDeviceToDevice);
    cudaMemcpyToSymbolAsync(c_c5b,  d_in[idx_c5b],  Cn*4,   0, cudaMemcpyDeviceToDevice);
    cudaMemcpyToSymbolAsync(c_n2w,  d_in[idx_n2w],  Cn*4,   0, cudaMemcpyDeviceToDevice);
    cudaMemcpyToSymbolAsync(c_n2b,  d_in[idx_n2b],  Cn*4,   0, cudaMemcpyDeviceToDevice);
    cudaMemcpyToSymbolAsync(c_ldww, d_in[idx_ldww], Cn*9*4, 0, cudaMemcpyDeviceToDevice);
    cudaMemcpyToSymbolAsync(c_ldwb, d_in[idx_ldwb], Cn*4,   0, cudaMemcpyDeviceToDevice);
    cudaMemcpyToSymbolAsync(c_lpwb, d_in[idx_lpwb], Cn*4,   0, cudaMemcpyDeviceToDevice);

    const int smem2 = Cn * R2 * R2 * 4;                     // 204800
    const int smem3 = (Cn*WPAD + Cn*64 + Cn*R3*R3) * 4;     // 151552
    cudaFuncSetAttribute(k2_mix,   cudaFuncAttributeMaxDynamicSharedMemorySize, smem2);
    cudaFuncSetAttribute(k3_final, cudaFuncAttributeMaxDynamicSharedMemorySize, smem3);

    k1_stats<<<NPIX/256, 256>>>(x);
    k2_mix<<<dim3(Wn/T2, Hn/T2, Bn), 256, smem2>>>(x);
    k3_final<<<dim3(Wn/T3, Hn/T3, Bn), 256, smem3>>>((const float*)d_in[idx_lpw], (float*)d_out);
}

// round 4
// speedup vs baseline: 1.1666x; 1.1666x over previous
#include <cuda_runtime.h>
#include <math.h>

#define Bn 8
#define Cn 128
#define Hn 224
#define Wn 224
#define HWn (Hn*Wn)        // 50176
#define CHWn (Cn*HWn)      // 6422528
#define NPIX (Bn*HWn)      // 401408

// ---------------- scratch (static device globals; no allocation) ----------------
__device__ float g_y[(long long)Bn*CHWn];   // LN2-normalized, shuffled tensor (205.5 MB)
__device__ float g_m1[NPIX];
__device__ float g_r1[NPIX];
// packed small weights (gmem staging, filled by memcpy at launch)
__device__ float g_spw_w[4*32*32];   // [g][o][c], group order (s2,s4,s1,s3)
__device__ float g_spw_wT[4*32*32];  // [g][c][o]  (filled by k0_prep)
__device__ float g_pwT[Cn*Cn];       // [c][o]     (filled by k0_prep)
__device__ float g_spw_b[128];       // flat [ci]
__device__ float g_c5w[128*9];
__device__ float g_c5b[128];
__device__ float g_n2w[128];
__device__ float g_n2b[128];

// ---------------- constant weights (warp-uniform access only) ----------------
__constant__ float c_n1w[Cn], c_n1b[Cn];
__constant__ float c_sdw_w[4][32][9];   // group order (s2,s4,s1,s3)
__constant__ float c_sdw_b[4][32];
__constant__ float c_ldww[Cn][9];
__constant__ float c_ldwb[Cn];
__constant__ float c_lpwb[Cn];

__device__ __forceinline__ float gelu_exact(float x) {
    return 0.5f * x * (1.0f + erff(x * 0.70710678118654752f));
}

// ================= kernel 0: transpose pw weights in gmem =================
__global__ __launch_bounds__(256) void k0_prep(const float* __restrict__ pw)
{
    int i = blockIdx.x * 256 + threadIdx.x;
    if (i < Cn*Cn) {
        int o = i >> 7, c = i & 127;          // read [o][c] coalesced
        g_pwT[c * Cn + o] = pw[i];
    }
    if (i < 4096) {
        int g = i >> 10, r = i & 1023, o = r >> 5, c = r & 31;  // read [g][o][c] coalesced
        g_spw_wT[g*1024 + c*32 + o] = g_spw_w[i];
    }
}

// ================= kernel 1: LN1 stats (mean, rstd per pixel) =================
__global__ __launch_bounds__(256) void k1_stats(const float* __restrict__ x)
{
    int idx = blockIdx.x * 256 + threadIdx.x;
    int b  = idx / HWn;
    int hw = idx - b * HWn;
    const float* px = x + b * CHWn + hw;
    float s = 0.f, ss = 0.f;
    #pragma unroll 8
    for (int ch = 0; ch < Cn; ch++) {
        float v = px[ch * HWn];
        s += v; ss = fmaf(v, v, ss);
    }
    float m = s * (1.0f/128.0f);
    float var = fmaf(-m, m, ss * (1.0f/128.0f));
    g_m1[idx] = m;
    g_r1[idx] = rsqrtf(var + 1e-6f);
}

// ================= kernel 2: branches + c5 + shuffle + LN2 (fused) =================
// tile 8x8 px, halo 2. 256 threads.
#define T2 8
#define R2 12
// smem layout (floats)
#define OFF_SX   0                         // [128][144]
#define OFF_ST   (OFF_SX + Cn*R2*R2)       // 18432: t [128][64]
#define OFF_W2   (OFF_ST + Cn*64)          // 26624: spw_wT [4][32c][32o]
#define OFF_RED  (OFF_W2 + 4096)           // 30720: [2][16][64]
#define OFF_MS   (OFF_RED + 2048)          // 32768
#define OFF_RS   (OFF_MS + 64)
#define OFF_GAM  (OFF_RS + 64)             // n2w per post-shuffle ch
#define OFF_BET  (OFF_GAM + 128)
#define OFF_C5W  (OFF_BET + 128)           // 33152: [128][9]
#define OFF_C5B  (OFF_C5W + 1152)
#define OFF_PWB  (OFF_C5B + 128)
#define OFF_SM1  (OFF_PWB + 128)           // stat mean halo [144]
#define OFF_SR1  (OFF_SM1 + 144)
#define SMEM2_FLOATS (OFF_SR1 + 144)       // 34848 floats = 139392 B

__global__ __launch_bounds__(256, 1) void k2_mix(const float* __restrict__ x)
{
    extern __shared__ float sm[];
    const int b  = blockIdx.z;
    const int h0 = blockIdx.y * T2;
    const int w0 = blockIdx.x * T2;
    const int tid = threadIdx.x;
    const int wid = tid >> 5, lane = tid & 31;
    const long long xb = (long long)b * CHWn;

    // ---- stage stats halo + small weight tables ----
    if (tid < 144) {
        int r = tid / 12, cc = tid - r * 12;
        int gh = h0 + r - 2, gw = w0 + cc - 2;
        float m = 0.f, rs = 0.f;
        if ((unsigned)gh < (unsigned)Hn && (unsigned)gw < (unsigned)Wn) {
            int p = b * HWn + gh * Wn + gw;
            m = g_m1[p]; rs = g_r1[p];
        }
        sm[OFF_SM1 + tid] = m; sm[OFF_SR1 + tid] = rs;
    }
    for (int i = tid; i < 4096; i += 256) sm[OFF_W2 + i] = g_spw_wT[i];   // [g][c][o], coalesced both sides
    for (int i = tid; i < 1152; i += 256) sm[OFF_C5W + i] = g_c5w[i];
    if (tid < 128) {
        sm[OFF_C5B + tid] = g_c5b[tid];
        sm[OFF_PWB + tid] = g_spw_b[tid];
        sm[OFF_GAM + tid] = g_n2w[tid];
        sm[OFF_BET + tid] = g_n2b[tid];
    }
    __syncthreads();

    // ---- stage LN1(x) tile, warp-per-channel (uniform cmem access) ----
    for (int ch = wid; ch < Cn; ch += 8) {
        const float gam = c_n1w[ch], bet = c_n1b[ch];
        const float* xc = x + xb + (long long)ch * HWn;
        for (int pos = lane; pos < 144; pos += 32) {
            int r = pos / 12, cc = pos - r * 12;
            int gh = h0 + r - 2, gw = w0 + cc - 2;
            float v = 0.f;
            if ((unsigned)gh < (unsigned)Hn && (unsigned)gw < (unsigned)Wn)
                v = (xc[gh * Wn + gw] - sm[OFF_SM1 + pos]) * sm[OFF_SR1 + pos] * gam + bet;
            sm[OFF_SX + ch * 144 + pos] = v;
        }
    }
    __syncthreads();

    // ---- phase B: t[ch][px] = gelu(dw3(shifted LN1 x)), ch warp-uniform ----
    const int px  = tid & 63;
    const int py0 = px >> 3, px0 = px & 7;
    {
        const int h = h0 + py0, w = w0 + px0;
        bool my[3], mx[3];
        #pragma unroll
        for (int k = 0; k < 3; k++) {
            my[k] = (unsigned)(h + k - 1) < (unsigned)Hn;
            mx[k] = (unsigned)(w + k - 1) < (unsigned)Wn;
        }
        #pragma unroll 4
        for (int it = 0; it < 32; it++) {
            const int ch = (tid >> 6) + it * 4;        // warp-uniform
            const int gg = ch >> 5, cc = ch & 31;
            const int srcb = ((0x2031 >> (4*gg)) & 15) << 5;     // {32,96,0,64}
            const int offy = (0x2002 >> (4*gg)) & 15;            // 1 - shh
            const int offx = (0x2020 >> (4*gg)) & 15;            // 1 - shw
            const float* bp = sm + OFF_SX + (srcb + cc) * 144 + (py0 + offy) * 12 + (px0 + offx);
            float a = c_sdw_b[gg][cc];
            #pragma unroll
            for (int dy = 0; dy < 3; dy++)
                #pragma unroll
                for (int dx = 0; dx < 3; dx++)
                    if (my[dy] && mx[dx])
                        a = fmaf(c_sdw_w[gg][cc][dy*3+dx], bp[dy*12+dx], a);
            sm[OFF_ST + ch * 64 + px] = gelu_exact(a);
        }
    }
    __syncthreads();

    // ---- phase C: pw GEMM (block-diag 32x32) + c5 residual ----
    const int o0 = (tid >> 4) * 8;       // 8 output channels (one group)
    const int q  = (tid & 15) * 4;       // 4 consecutive pixels (same row)
    const int g  = o0 >> 5, ol = o0 & 31;
    const int qy = q >> 3, qx = q & 7;

    float acc[8][4];
    #pragma unroll
    for (int j = 0; j < 8; j++) {
        float bj = sm[OFF_PWB + o0 + j];
        acc[j][0] = bj; acc[j][1] = bj; acc[j][2] = bj; acc[j][3] = bj;
    }
    {
        const float* w2g = sm + OFF_W2 + g * 1024 + ol;
        const float* stg = sm + OFF_ST + (g * 32) * 64 + q;
        #pragma unroll 8
        for (int c = 0; c < 32; c++) {
            float4 wa = *(const float4*)(w2g + c * 32);
            float4 wb = *(const float4*)(w2g + c * 32 + 4);
            float4 tv = *(const float4*)(stg + c * 64);
            acc[0][0]=fmaf(wa.x,tv.x,acc[0][0]); acc[0][1]=fmaf(wa.x,tv.y,acc[0][1]); acc[0][2]=fmaf(wa.x,tv.z,acc[0][2]); acc[0][3]=fmaf(wa.x,tv.w,acc[0][3]);
            acc[1][0]=fmaf(wa.y,tv.x,acc[1][0]); acc[1][1]=fmaf(wa.y,tv.y,acc[1][1]); acc[1][2]=fmaf(wa.y,tv.z,acc[1][2]); acc[1][3]=fmaf(wa.y,tv.w,acc[1][3]);
            acc[2][0]=fmaf(wa.z,tv.x,acc[2][0]); acc[2][1]=fmaf(wa.z,tv.y,acc[2][1]); acc[2][2]=fmaf(wa.z,tv.z,acc[2][2]); acc[2][3]=fmaf(wa.z,tv.w,acc[2][3]);
            acc[3][0]=fmaf(wa.w,tv.x,acc[3][0]); acc[3][1]=fmaf(wa.w,tv.y,acc[3][1]); acc[3][2]=fmaf(wa.w,tv.z,acc[3][2]); acc[3][3]=fmaf(wa.w,tv.w,acc[3][3]);
            acc[4][0]=fmaf(wb.x,tv.x,acc[4][0]); acc[4][1]=fmaf(wb.x,tv.y,acc[4][1]); acc[4][2]=fmaf(wb.x,tv.z,acc[4][2]); acc[4][3]=fmaf(wb.x,tv.w,acc[4][3]);
            acc[5][0]=fmaf(wb.y,tv.x,acc[5][0]); acc[5][1]=fmaf(wb.y,tv.y,acc[5][1]); acc[5][2]=fmaf(wb.y,tv.z,acc[5][2]); acc[5][3]=fmaf(wb.y,tv.w,acc[5][3]);
            acc[6][0]=fmaf(wb.z,tv.x,acc[6][0]); acc[6][1]=fmaf(wb.z,tv.y,acc[6][1]); acc[6][2]=fmaf(wb.z,tv.z,acc[6][2]); acc[6][3]=fmaf(wb.z,tv.w,acc[6][3]);
            acc[7][0]=fmaf(wb.w,tv.x,acc[7][0]); acc[7][1]=fmaf(wb.w,tv.y,acc[7][1]); acc[7][2]=fmaf(wb.w,tv.z,acc[7][2]); acc[7][3]=fmaf(wb.w,tv.w,acc[7][3]);
        }
    }
    // c5 residual (unshifted dw3 of LN1(x); zero halo = SAME pad)
    #pragma unroll
    for (int j = 0; j < 8; j++) {
        const int ci = o0 + j;
        const float* cw = sm + OFF_C5W + ci * 9;
        const float* bp = sm + OFF_SX + ci * 144 + (qy + 1) * 12 + (qx + 1);
        const float b5 = sm[OFF_C5B + ci];
        #pragma unroll
        for (int i = 0; i < 4; i++) {
            float a5 = b5;
            #pragma unroll
            for (int k = 0; k < 9; k++)
                a5 = fmaf(cw[k], bp[(k/3)*12 + (k%3) + i], a5);
            acc[j][i] += a5;
        }
    }
    // ---- LN2 stats: reduce across the 16 o-groups ----
    {
        float ps[4] = {0,0,0,0}, pq[4] = {0,0,0,0};
        #pragma unroll
        for (int j = 0; j < 8; j++)
            #pragma unroll
            for (int i = 0; i < 4; i++) { ps[i] += acc[j][i]; pq[i] = fmaf(acc[j][i], acc[j][i], pq[i]); }
        #pragma unroll
        for (int i = 0; i < 4; i++) {
            sm[OFF_RED + (tid >> 4) * 64 + q + i]        = ps[i];
            sm[OFF_RED + 1024 + (tid >> 4) * 64 + q + i] = pq[i];
        }
    }
    __syncthreads();
    if (tid < 64) {
        float s = 0.f, ss = 0.f;
        #pragma unroll
        for (int r = 0; r < 16; r++) {
            s  += sm[OFF_RED + r * 64 + tid];
            ss += sm[OFF_RED + 1024 + r * 64 + tid];
        }
        float m = s * (1.0f/128.0f);
        float var = fmaf(-m, m, ss * (1.0f/128.0f));
        sm[OFF_MS + tid] = m;
        sm[OFF_RS + tid] = rsqrtf(var + 1e-6f);
    }
    __syncthreads();

    // ---- normalize (LN2) + shuffle + store ----
    float mv[4], rv[4];
    #pragma unroll
    for (int i = 0; i < 4; i++) { mv[i] = sm[OFF_MS + q + i]; rv[i] = sm[OFF_RS + q + i]; }
    const long long obase = xb + (long long)(h0 + qy) * Wn + (w0 + qx);
    #pragma unroll
    for (int j = 0; j < 8; j++) {
        const int ci = o0 + j;
        const int ko = ((ci & 63) << 1) | (ci >> 6);   // channel shuffle, 2 groups
        const float gam = sm[OFF_GAM + ko], bet = sm[OFF_BET + ko];
        float4 ov;
        ov.x = fmaf((acc[j][0] - mv[0]) * rv[0], gam, bet);
        ov.y = fmaf((acc[j][1] - mv[1]) * rv[1], gam, bet);
        ov.z = fmaf((acc[j][2] - mv[2]) * rv[2], gam, bet);
        ov.w = fmaf((acc[j][3] - mv[3]) * rv[3], gam, bet);
        *(float4*)&g_y[obase + (long long)ko * HWn] = ov;
    }
}

// ================= kernel 3: dw3(gelu) + pw 128x128 GEMM =================
// tile 16w x 8h = 128 px; thread tile 8o x 8px; channel-halved staging.
#define T3W 16
#define T3H 8
#define R3H 10
#define R3W 18
#define WP3 132
#define OFF3_W 0                      // [128][132]
#define OFF3_G (Cn*WP3)               // 16896: [128][128]
#define OFF3_Y (OFF3_G + Cn*128)      // 33280: [64][180]
#define SMEM3_FLOATS (OFF3_Y + 64*R3H*R3W)   // 44800 floats = 179200 B

__global__ __launch_bounds__(256, 1) void k3_final(float* __restrict__ out)
{
    extern __shared__ float sm[];
    const int b  = blockIdx.z;
    const int h0 = blockIdx.y * T3H;
    const int w0 = blockIdx.x * T3W;
    const int tid = threadIdx.x;
    const long long xb = (long long)b * CHWn;

    // stage transposed pw weights: coalesced read, conflict-free-ish write
    for (int i = tid; i < Cn * Cn; i += 256) {
        int c = i >> 7, o = i & 127;
        sm[OFF3_W + c * WP3 + o] = g_pwT[i];
    }

    // two channel halves: stage y tile -> gelu(dw3) into gsm
    for (int h2 = 0; h2 < 2; h2++) {
        for (int i = tid; i < 64 * R3H * R3W; i += 256) {
            int ch = i / (R3H * R3W);
            int pos = i - ch * (R3H * R3W);
            int r = pos / R3W, cc = pos - r * R3W;
            int gh = h0 + r - 1, gw = w0 + cc - 1;
            float v = 0.f;
            if ((unsigned)gh < (unsigned)Hn && (unsigned)gw < (unsigned)Wn)
                v = g_y[xb + (long long)(h2 * 64 + ch) * HWn + gh * Wn + gw];
            sm[OFF3_Y + i] = v;
        }
        __syncthreads();
        for (int i = tid; i < 64 * 128; i += 256) {
            int chl = i >> 7, p = i & 127;        // chl warp-uniform
            int ch = h2 * 64 + chl;
            int py = p >> 4, pxx = p & 15;
            const float* bp = sm + OFF3_Y + chl * (R3H * R3W) + py * R3W + pxx;
            float a = c_ldwb[ch];
            #pragma unroll
            for (int k = 0; k < 9; k++)
                a = fmaf(c_ldww[ch][k], bp[(k/3)*R3W + (k%3)], a);
            sm[OFF3_G + ch * 128 + p] = gelu_exact(a);
        }
        __syncthreads();
    }

    // register-blocked GEMM: 8 o x 8 px per thread
    const int o0 = (tid >> 4) * 8;
    const int q  = (tid & 15) * 8;         // 8 px, all in one 16-wide row
    float acc[8][8];
    #pragma unroll
    for (int j = 0; j < 8; j++) {
        float bj = c_lpwb[o0 + j];
        #pragma unroll
        for (int i = 0; i < 8; i++) acc[j][i] = bj;
    }
    {
        const float* Wp = sm + OFF3_W + o0;
        const float* Gp = sm + OFF3_G + q;
        #pragma unroll 4
        for (int c = 0; c < Cn; c++) {
            float4 wa = *(const float4*)(Wp + c * WP3);
            float4 wb = *(const float4*)(Wp + c * WP3 + 4);
            float4 ga = *(const float4*)(Gp + c * 128);
            float4 gb = *(const float4*)(Gp + c * 128 + 4);
            float wv[8] = {wa.x,wa.y,wa.z,wa.w,wb.x,wb.y,wb.z,wb.w};
            float gv[8] = {ga.x,ga.y,ga.z,ga.w,gb.x,gb.y,gb.z,gb.w};
            #pragma unroll
            for (int j = 0; j < 8; j++)
                #pragma unroll
                for (int i = 0; i < 8; i++)
                    acc[j][i] = fmaf(wv[j], gv[i], acc[j][i]);
        }
    }
    // store
    const int row = q >> 4, col = q & 15;
    const long long obase = xb + (long long)(h0 + row) * Wn + (w0 + col);
    #pragma unroll
    for (int j = 0; j < 8; j++) {
        float4 v0 = make_float4(acc[j][0], acc[j][1], acc[j][2], acc[j][3]);
        float4 v1 = make_float4(acc[j][4], acc[j][5], acc[j][6], acc[j][7]);
        float* op = out + obase + (long long)(o0 + j) * HWn;
        *(float4*)op = v0;
        *(float4*)(op + 4) = v1;
    }
}

// ================= launch =================
extern "C" void kernel_launch(void* const* d_in, const int* in_sizes, int n_in,
                              void* d_out, int out_size)
{
    (void)out_size;
    // resolve inputs by element count (order-agnostic; each _b follows its _w)
    int idx_x = 0, idx_lpw = -1, idx_c5w = -1, idx_ldww = -1;
    int dw_w[4] = {-1,-1,-1,-1}, pw_w[4] = {-1,-1,-1,-1};
    int ndw = 0, npw = 0;
    for (int i = 0; i < n_in; i++) {
        int s = in_sizes[i];
        if (s > 100000)      idx_x = i;
        else if (s == 16384) idx_lpw = i;
        else if (s == 1152)  { if (idx_c5w < 0) idx_c5w = i; else idx_ldww = i; }
        else if (s == 288 && ndw < 4)  dw_w[ndw++] = i;
        else if (s == 1024 && npw < 4) pw_w[npw++] = i;
    }
    const int idx_c5b  = idx_c5w  + 1;
    const int idx_ldwb = idx_ldww + 1;
    const int idx_lpwb = idx_lpw  + 1;
    int v128[8]; int nv = 0;
    for (int i = 0; i < n_in; i++)
        if (in_sizes[i] == 128 && i != idx_c5b && i != idx_ldwb && i != idx_lpwb && nv < 8)
            v128[nv++] = i;
    const int idx_n1w = v128[0], idx_n1b = v128[1];
    const int idx_n2w = v128[2], idx_n2b = v128[3];

    const float* x = (const float*)d_in[idx_x];

    cudaMemcpyToSymbolAsync(c_n1w, d_in[idx_n1w], Cn*4, 0, cudaMemcpyDeviceToDevice);
    cudaMemcpyToSymbolAsync(c_n1b, d_in[idx_n1b], Cn*4, 0, cudaMemcpyDeviceToDevice);
    const int GS[4] = {1, 3, 0, 2};   // group order s2,s4,s1,s3
    for (int g = 0; g < 4; g++) {
        int sb = GS[g];
        cudaMemcpyToSymbolAsync(c_sdw_w,  d_in[dw_w[sb]],     32*9*4,  g*32*9*4,  cudaMemcpyDeviceToDevice);
        cudaMemcpyToSymbolAsync(c_sdw_b,  d_in[dw_w[sb] + 1], 32*4,    g*32*4,    cudaMemcpyDeviceToDevice);
        cudaMemcpyToSymbolAsync(g_spw_w,  d_in[pw_w[sb]],     32*32*4, g*32*32*4, cudaMemcpyDeviceToDevice);
        cudaMemcpyToSymbolAsync(g_spw_b,  d_in[pw_w[sb] + 1], 32*4,    g*32*4,    cudaMemcpyDeviceToDevice);
    }
    cudaMemcpyToSymbolAsync(g_c5w,  d_in[idx_c5w],  Cn*9*4, 0, cudaMemcpyDeviceToDevice);
    cudaMemcpyToSymbolAsync(g_c5b,  d_in[idx_c5b],  Cn*4,   0, cudaMemcpyDeviceToDevice);
    cudaMemcpyToSymbolAsync(g_n2w,  d_in[idx_n2w],  Cn*4,   0, cudaMemcpyDeviceToDevice);
    cudaMemcpyToSymbolAsync(g_n2b,  d_in[idx_n2b],  Cn*4,   0, cudaMemcpyDeviceToDevice);
    cudaMemcpyToSymbolAsync(c_ldww, d_in[idx_ldww], Cn*9*4, 0, cudaMemcpyDeviceToDevice);
    cudaMemcpyToSymbolAsync(c_ldwb, d_in[idx_ldwb], Cn*4,   0, cudaMemcpyDeviceToDevice);
    cudaMemcpyToSymbolAsync(c_lpwb, d_in[idx_lpwb], Cn*4,   0, cudaMemcpyDeviceToDevice);

    const int smem2 = SMEM2_FLOATS * 4;
    const int smem3 = SMEM3_FLOATS * 4;
    cudaFuncSetAttribute(k2_mix,   cudaFuncAttributeMaxDynamicSharedMemorySize, smem2);
    cudaFuncSetAttribute(k3_final, cudaFuncAttributeMaxDynamicSharedMemorySize, smem3);

    k0_prep<<<64, 256>>>((const float*)d_in[idx_lpw]);
    k1_stats<<<NPIX/256, 256>>>(x);
    k2_mix<<<dim3(Wn/T2, Hn/T2, Bn), 256, smem2>>>(x);
    k3_final<<<dim3(Wn/T3W, Hn/T3H, Bn), 256, smem3>>>((float*)d_out);
}

// round 6
// speedup vs baseline: 1.6264x; 1.3941x over previous
#include <cuda_runtime.h>
#include <math.h>

#define Bn 8
#define Cn 128
#define Hn 224
#define Wn 224
#define HWn (Hn*Wn)        // 50176
#define CHWn (Cn*HWn)      // 6422528
#define NPIX (Bn*HWn)      // 401408

// ---------------- scratch (static device globals; no allocation) ----------------
__device__ float g_y[(long long)Bn*CHWn];   // LN2-normalized, shuffled tensor (205.5 MB)
__device__ float g_m1[NPIX];
__device__ float g_r1[NPIX];
// packed small weights (gmem staging, filled by memcpy at launch)
__device__ float g_spw_w[4*32*32];   // [g][o][c], group order (s2,s4,s1,s3)
__device__ float g_spw_wT[4*32*32];  // [g][c][o]  (filled by k0_prep)
__device__ float g_pwT[Cn*Cn];       // [c][o]     (filled by k0_prep)
__device__ float g_spw_b[128];       // flat [ci]
__device__ float g_c5w[128*9];
__device__ float g_c5b[128];
__device__ float g_n2w[128];
__device__ float g_n2b[128];

// ---------------- constant weights (warp-uniform access only) ----------------
__constant__ float c_n1w[Cn], c_n1b[Cn];
__constant__ float c_sdw_w[4][32][9];   // group order (s2,s4,s1,s3)
__constant__ float c_sdw_b[4][32];
__constant__ float c_ldww[Cn][9];
__constant__ float c_ldwb[Cn];
__constant__ float c_lpwb[Cn];

__device__ __forceinline__ float gelu_exact(float x) {
    return 0.5f * x * (1.0f + erff(x * 0.70710678118654752f));
}

// ================= kernel 0: transpose pw weights in gmem =================
__global__ __launch_bounds__(256) void k0_prep(const float* __restrict__ pw)
{
    int i = blockIdx.x * 256 + threadIdx.x;
    if (i < Cn*Cn) {
        int o = i >> 7, c = i & 127;          // read [o][c] coalesced
        g_pwT[c * Cn + o] = pw[i];
    }
    if (i < 4096) {
        int g = i >> 10, r = i & 1023, o = r >> 5, c = r & 31;  // read [g][o][c] coalesced
        g_spw_wT[g*1024 + c*32 + o] = g_spw_w[i];
    }
}

// ================= kernel 1: LN1 stats (mean, rstd per pixel) =================
__global__ __launch_bounds__(256) void k1_stats(const float* __restrict__ x)
{
    int idx = blockIdx.x * 256 + threadIdx.x;
    int b  = idx / HWn;
    int hw = idx - b * HWn;
    const float* px = x + b * CHWn + hw;
    float s = 0.f, ss = 0.f;
    #pragma unroll 8
    for (int ch = 0; ch < Cn; ch++) {
        float v = px[ch * HWn];
        s += v; ss = fmaf(v, v, ss);
    }
    float m = s * (1.0f/128.0f);
    float var = fmaf(-m, m, ss * (1.0f/128.0f));
    g_m1[idx] = m;
    g_r1[idx] = rsqrtf(var + 1e-6f);
}

// ================= kernel 2: branches + c5 + shuffle + LN2 (fused) =================
// tile 8x8 px, halo 2. 512 threads (16 warps) for latency hiding.
#define T2 8
#define R2 12
#define NT2 512
// smem layout (floats)
#define OFF_SX   0                         // [128][144]
#define OFF_ST   (OFF_SX + Cn*R2*R2)       // 18432: t [128][64]
#define OFF_W2   (OFF_ST + Cn*64)          // 26624: spw_wT [4][32c][32o]
#define OFF_RED  (OFF_W2 + 4096)           // 30720: [2][32][64]
#define OFF_MS   (OFF_RED + 4096)          // 34816
#define OFF_RS   (OFF_MS + 64)
#define OFF_GAM  (OFF_RS + 64)             // n2w per post-shuffle ch
#define OFF_BET  (OFF_GAM + 128)
#define OFF_C5W  (OFF_BET + 128)           // [128][9]
#define OFF_C5B  (OFF_C5W + 1152)
#define OFF_PWB  (OFF_C5B + 128)
#define OFF_SM1  (OFF_PWB + 128)           // stat mean halo [144]
#define OFF_SR1  (OFF_SM1 + 144)
#define SMEM2_FLOATS (OFF_SR1 + 144)       // 36896 floats = 147584 B

__global__ __launch_bounds__(NT2, 1) void k2_mix(const float* __restrict__ x)
{
    extern __shared__ float sm[];
    const int b  = blockIdx.z;
    const int h0 = blockIdx.y * T2;
    const int w0 = blockIdx.x * T2;
    const int tid = threadIdx.x;
    const int wid = tid >> 5, lane = tid & 31;
    const long long xb = (long long)b * CHWn;

    // ---- stage stats halo + small weight tables ----
    if (tid < 144) {
        int r = tid / 12, cc = tid - r * 12;
        int gh = h0 + r - 2, gw = w0 + cc - 2;
        float m = 0.f, rs = 0.f;
        if ((unsigned)gh < (unsigned)Hn && (unsigned)gw < (unsigned)Wn) {
            int p = b * HWn + gh * Wn + gw;
            m = g_m1[p]; rs = g_r1[p];
        }
        sm[OFF_SM1 + tid] = m; sm[OFF_SR1 + tid] = rs;
    }
    for (int i = tid; i < 4096; i += NT2) sm[OFF_W2 + i] = g_spw_wT[i];   // coalesced both sides
    for (int i = tid; i < 1152; i += NT2) sm[OFF_C5W + i] = g_c5w[i];
    if (tid < 128) {
        sm[OFF_C5B + tid] = g_c5b[tid];
        sm[OFF_PWB + tid] = g_spw_b[tid];
        sm[OFF_GAM + tid] = g_n2w[tid];
        sm[OFF_BET + tid] = g_n2b[tid];
    }
    __syncthreads();

    // ---- stage LN1(x) tile, warp-per-channel (uniform cmem access) ----
    for (int ch = wid; ch < Cn; ch += 16) {
        const float gam = c_n1w[ch], bet = c_n1b[ch];
        const float* xc = x + xb + (long long)ch * HWn;
        for (int pos = lane; pos < 144; pos += 32) {
            int r = pos / 12, cc = pos - r * 12;
            int gh = h0 + r - 2, gw = w0 + cc - 2;
            float v = 0.f;
            if ((unsigned)gh < (unsigned)Hn && (unsigned)gw < (unsigned)Wn)
                v = (xc[gh * Wn + gw] - sm[OFF_SM1 + pos]) * sm[OFF_SR1 + pos] * gam + bet;
            sm[OFF_SX + ch * 144 + pos] = v;
        }
    }
    __syncthreads();

    // ---- phase B: t[ch][px] = gelu(dw3(shifted LN1 x)), ch warp-uniform ----
    const int px  = tid & 63;
    const int py0 = px >> 3, px0 = px & 7;
    {
        const int h = h0 + py0, w = w0 + px0;
        bool my[3], mx[3];
        #pragma unroll
        for (int k = 0; k < 3; k++) {
            my[k] = (unsigned)(h + k - 1) < (unsigned)Hn;
            mx[k] = (unsigned)(w + k - 1) < (unsigned)Wn;
        }
        #pragma unroll 4
        for (int it = 0; it < 16; it++) {
            const int ch = (tid >> 6) + it * 8;        // warp-uniform
            const int gg = ch >> 5, cc = ch & 31;
            const int srcb = ((0x2031 >> (4*gg)) & 15) << 5;     // {32,96,0,64}
            const int offy = (0x2002 >> (4*gg)) & 15;            // 1 - shh
            const int offx = (0x2020 >> (4*gg)) & 15;            // 1 - shw
            const float* bp = sm + OFF_SX + (srcb + cc) * 144 + (py0 + offy) * 12 + (px0 + offx);
            float a = c_sdw_b[gg][cc];
            #pragma unroll
            for (int dy = 0; dy < 3; dy++)
                #pragma unroll
                for (int dx = 0; dx < 3; dx++)
                    if (my[dy] && mx[dx])
                        a = fmaf(c_sdw_w[gg][cc][dy*3+dx], bp[dy*12+dx], a);
            sm[OFF_ST + ch * 64 + px] = gelu_exact(a);
        }
    }
    __syncthreads();

    // ---- phase C: pw GEMM (block-diag 32x32) + c5 residual ----
    const int o0 = (tid >> 4) * 4;       // 4 output channels
    const int q  = (tid & 15) * 4;       // 4 consecutive pixels (same row)
    const int g  = o0 >> 5, ol = o0 & 31;
    const int qy = q >> 3, qx = q & 7;

    float acc[4][4];
    #pragma unroll
    for (int j = 0; j < 4; j++) {
        float bj = sm[OFF_PWB + o0 + j];
        acc[j][0] = bj; acc[j][1] = bj; acc[j][2] = bj; acc[j][3] = bj;
    }
    {
        const float* w2g = sm + OFF_W2 + g * 1024 + ol;
        const float* stg = sm + OFF_ST + (g * 32) * 64 + q;
        #pragma unroll 8
        for (int c = 0; c < 32; c++) {
            float4 wa = *(const float4*)(w2g + c * 32);
            float4 tv = *(const float4*)(stg + c * 64);
            acc[0][0]=fmaf(wa.x,tv.x,acc[0][0]); acc[0][1]=fmaf(wa.x,tv.y,acc[0][1]); acc[0][2]=fmaf(wa.x,tv.z,acc[0][2]); acc[0][3]=fmaf(wa.x,tv.w,acc[0][3]);
            acc[1][0]=fmaf(wa.y,tv.x,acc[1][0]); acc[1][1]=fmaf(wa.y,tv.y,acc[1][1]); acc[1][2]=fmaf(wa.y,tv.z,acc[1][2]); acc[1][3]=fmaf(wa.y,tv.w,acc[1][3]);
            acc[2][0]=fmaf(wa.z,tv.x,acc[2][0]); acc[2][1]=fmaf(wa.z,tv.y,acc[2][1]); acc[2][2]=fmaf(wa.z,tv.z,acc[2][2]); acc[2][3]=fmaf(wa.z,tv.w,acc[2][3]);
            acc[3][0]=fmaf(wa.w,tv.x,acc[3][0]); acc[3][1]=fmaf(wa.w,tv.y,acc[3][1]); acc[3][2]=fmaf(wa.w,tv.z,acc[3][2]); acc[3][3]=fmaf(wa.w,tv.w,acc[3][3]);
        }
    }
    // c5 residual (unshifted dw3 of LN1(x); zero halo = SAME pad)
    #pragma unroll
    for (int j = 0; j < 4; j++) {
        const int ci = o0 + j;
        const float* cw = sm + OFF_C5W + ci * 9;
        const float* bp = sm + OFF_SX + ci * 144 + (qy + 1) * 12 + (qx + 1);
        const float b5 = sm[OFF_C5B + ci];
        #pragma unroll
        for (int i = 0; i < 4; i++) {
            float a5 = b5;
            #pragma unroll
            for (int k = 0; k < 9; k++)
                a5 = fmaf(cw[k], bp[(k/3)*12 + (k%3) + i], a5);
            acc[j][i] += a5;
        }
    }
    // ---- LN2 stats: reduce across the 32 o-groups ----
    {
        float ps[4] = {0,0,0,0}, pq[4] = {0,0,0,0};
        #pragma unroll
        for (int j = 0; j < 4; j++)
            #pragma unroll
            for (int i = 0; i < 4; i++) { ps[i] += acc[j][i]; pq[i] = fmaf(acc[j][i], acc[j][i], pq[i]); }
        #pragma unroll
        for (int i = 0; i < 4; i++) {
            sm[OFF_RED + (tid >> 4) * 64 + q + i]        = ps[i];
            sm[OFF_RED + 2048 + (tid >> 4) * 64 + q + i] = pq[i];
        }
    }
    __syncthreads();
    if (tid < 64) {
        float s = 0.f, ss = 0.f;
        #pragma unroll
        for (int r = 0; r < 32; r++) {
            s  += sm[OFF_RED + r * 64 + tid];
            ss += sm[OFF_RED + 2048 + r * 64 + tid];
        }
        float m = s * (1.0f/128.0f);
        float var = fmaf(-m, m, ss * (1.0f/128.0f));
        sm[OFF_MS + tid] = m;
        sm[OFF_RS + tid] = rsqrtf(var + 1e-6f);
    }
    __syncthreads();

    // ---- normalize (LN2) + shuffle + store ----
    float mv[4], rv[4];
    #pragma unroll
    for (int i = 0; i < 4; i++) { mv[i] = sm[OFF_MS + q + i]; rv[i] = sm[OFF_RS + q + i]; }
    const long long obase = xb + (long long)(h0 + qy) * Wn + (w0 + qx);
    #pragma unroll
    for (int j = 0; j < 4; j++) {
        const int ci = o0 + j;
        const int ko = ((ci & 63) << 1) | (ci >> 6);   // channel shuffle, 2 groups
        const float gam = sm[OFF_GAM + ko], bet = sm[OFF_BET + ko];
        float4 ov;
        ov.x = fmaf((acc[j][0] - mv[0]) * rv[0], gam, bet);
        ov.y = fmaf((acc[j][1] - mv[1]) * rv[1], gam, bet);
        ov.z = fmaf((acc[j][2] - mv[2]) * rv[2], gam, bet);
        ov.w = fmaf((acc[j][3] - mv[3]) * rv[3], gam, bet);
        *(float4*)&g_y[obase + (long long)ko * HWn] = ov;
    }
}

// ================= kernel 3: dw3(gelu) + pw 128x128 GEMM =================
// tile 16w x 8h = 128 px; 512 threads; thread tile 4o x 8px.
#define T3W 16
#define T3H 8
#define R3H 10
#define R3W 18
#define WP3 132
#define NT3 512
#define OFF3_W 0                      // [128][132]
#define OFF3_G (Cn*WP3)               // 16896: [128][128]
#define OFF3_Y (OFF3_G + Cn*128)      // 33280: [64][180]
#define SMEM3_FLOATS (OFF3_Y + 64*R3H*R3W)   // 44800 floats = 179200 B

__global__ __launch_bounds__(NT3, 1) void k3_final(float* __restrict__ out)
{
    extern __shared__ float sm[];
    const int b  = blockIdx.z;
    const int h0 = blockIdx.y * T3H;
    const int w0 = blockIdx.x * T3W;
    const int tid = threadIdx.x;
    const long long xb = (long long)b * CHWn;

    // stage transposed pw weights
    for (int i = tid; i < Cn * Cn; i += NT3) {
        int c = i >> 7, o = i & 127;
        sm[OFF3_W + c * WP3 + o] = g_pwT[i];
    }

    // two channel halves: stage y tile -> gelu(dw3) into gsm
    for (int h2 = 0; h2 < 2; h2++) {
        for (int i = tid; i < 64 * R3H * R3W; i += NT3) {
            int ch = i / (R3H * R3W);
            int pos = i - ch * (R3H * R3W);
            int r = pos / R3W, cc = pos - r * R3W;
            int gh = h0 + r - 1, gw = w0 + cc - 1;
            float v = 0.f;
            if ((unsigned)gh < (unsigned)Hn && (unsigned)gw < (unsigned)Wn)
                v = g_y[xb + (long long)(h2 * 64 + ch) * HWn + gh * Wn + gw];
            sm[OFF3_Y + i] = v;
        }
        __syncthreads();
        for (int i = tid; i < 64 * 128; i += NT3) {
            int chl = i >> 7, p = i & 127;        // chl warp-uniform
            int ch = h2 * 64 + chl;
            int py = p >> 4, pxx = p & 15;
            const float* bp = sm + OFF3_Y + chl * (R3H * R3W) + py * R3W + pxx;
            float a = c_ldwb[ch];
            #pragma unroll
            for (int k = 0; k < 9; k++)
                a = fmaf(c_ldww[ch][k], bp[(k/3)*R3W + (k%3)], a);
            sm[OFF3_G + ch * 128 + p] = gelu_exact(a);
        }
        __syncthreads();
    }

    // register-blocked GEMM: 4 o x 8 px per thread
    const int o0 = (tid >> 4) * 4;
    const int q  = (tid & 15) * 8;         // 8 px, all in one 16-wide row
    float acc[4][8];
    #pragma unroll
    for (int j = 0; j < 4; j++) {
        float bj = c_lpwb[o0 + j];
        #pragma unroll
        for (int i = 0; i < 8; i++) acc[j][i] = bj;
    }
    {
        const float* Wp = sm + OFF3_W + o0;
        const float* Gp = sm + OFF3_G + q;
        #pragma unroll 8
        for (int c = 0; c < Cn; c++) {
            float4 wa = *(const float4*)(Wp + c * WP3);
            float4 ga = *(const float4*)(Gp + c * 128);
            float4 gb = *(const float4*)(Gp + c * 128 + 4);
            float wv[4] = {wa.x,wa.y,wa.z,wa.w};
            float gv[8] = {ga.x,ga.y,ga.z,ga.w,gb.x,gb.y,gb.z,gb.w};
            #pragma unroll
            for (int j = 0; j < 4; j++)
                #pragma unroll
                for (int i = 0; i < 8; i++)
                    acc[j][i] = fmaf(wv[j], gv[i], acc[j][i]);
        }
    }
    // store
    const int row = q >> 4, col = q & 15;
    const long long obase = xb + (long long)(h0 + row) * Wn + (w0 + col);
    #pragma unroll
    for (int j = 0; j < 4; j++) {
        float4 v0 = make_float4(acc[j][0], acc[j][1], acc[j][2], acc[j][3]);
        float4 v1 = make_float4(acc[j][4], acc[j][5], acc[j][6], acc[j][7]);
        float* op = out + obase + (long long)(o0 + j) * HWn;
        *(float4*)op = v0;
        *(float4*)(op + 4) = v1;
    }
}

// ================= launch =================
extern "C" void kernel_launch(void* const* d_in, const int* in_sizes, int n_in,
                              void* d_out, int out_size)
{
    (void)out_size;
    // resolve inputs by element count (order-agnostic; each _b follows its _w)
    int idx_x = 0, idx_lpw = -1, idx_c5w = -1, idx_ldww = -1;
    int dw_w[4] = {-1,-1,-1,-1}, pw_w[4] = {-1,-1,-1,-1};
    int ndw = 0, npw = 0;
    for (int i = 0; i < n_in; i++) {
        int s = in_sizes[i];
        if (s > 100000)      idx_x = i;
        else if (s == 16384) idx_lpw = i;
        else if (s == 1152)  { if (idx_c5w < 0) idx_c5w = i; else idx_ldww = i; }
        else if (s == 288 && ndw < 4)  dw_w[ndw++] = i;
        else if (s == 1024 && npw < 4) pw_w[npw++] = i;
    }
    const int idx_c5b  = idx_c5w  + 1;
    const int idx_ldwb = idx_ldww + 1;
    const int idx_lpwb = idx_lpw  + 1;
    int v128[8]; int nv = 0;
    for (int i = 0; i < n_in; i++)
        if (in_sizes[i] == 128 && i != idx_c5b && i != idx_ldwb && i != idx_lpwb && nv < 8)
            v128[nv++] = i;
    const int idx_n1w = v128[0], idx_n1b = v128[1];
    const int idx_n2w = v128[2], idx_n2b = v128[3];

    const float* x = (const float*)d_in[idx_x];

    cudaMemcpyToSymbolAsync(c_n1w, d_in[idx_n1w], Cn*4, 0, cudaMemcpyDeviceToDevice);
    cudaMemcpyToSymbolAsync(c_n1b, d_in[idx_n1b], Cn*4, 0, cudaMemcpyDeviceToDevice);
    const int GS[4] = {1, 3, 0, 2};   // group order s2,s4,s1,s3
    for (int g = 0; g < 4; g++) {
        int sb = GS[g];
        cudaMemcpyToSymbolAsync(c_sdw_w,  d_in[dw_w[sb]],     32*9*4,  g*32*9*4,  cudaMemcpyDeviceToDevice);
        cudaMemcpyToSymbolAsync(c_sdw_b,  d_in[dw_w[sb] + 1], 32*4,    g*32*4,    cudaMemcpyDeviceToDevice);
        cudaMemcpyToSymbolAsync(g_spw_w,  d_in[pw_w[sb]],     32*32*4, g*32*32*4, cudaMemcpyDeviceToDevice);
        cudaMemcpyToSymbolAsync(g_spw_b,  d_in[pw_w[sb] + 1], 32*4,    g*32*4,    cudaMemcpyDeviceToDevice);
    }
    cudaMemcpyToSymbolAsync(g_c5w,  d_in[idx_c5w],  Cn*9*4, 0, cudaMemcpyDeviceToDevice);
    cudaMemcpyToSymbolAsync(g_c5b,  d_in[idx_c5b],  Cn*4,   0, cudaMemcpyDeviceToDevice);
    cudaMemcpyToSymbolAsync(g_n2w,  d_in[idx_n2w],  Cn*4,   0, cudaMemcpyDeviceToDevice);
    cudaMemcpyToSymbolAsync(g_n2b,  d_in[idx_n2b],  Cn*4,   0, cudaMemcpyDeviceToDevice);
    cudaMemcpyToSymbolAsync(c_ldww, d_in[idx_ldww], Cn*9*4, 0, cudaMemcpyDeviceToDevice);
    cudaMemcpyToSymbolAsync(c_ldwb, d_in[idx_ldwb], Cn*4,   0, cudaMemcpyDeviceToDevice);
    cudaMemcpyToSymbolAsync(c_lpwb, d_in[idx_lpwb], Cn*4,   0, cudaMemcpyDeviceToDevice);

    const int smem2 = SMEM2_FLOATS * 4;
    const int smem3 = SMEM3_FLOATS * 4;
    cudaFuncSetAttribute(k2_mix,   cudaFuncAttributeMaxDynamicSharedMemorySize, smem2);
    cudaFuncSetAttribute(k3_final, cudaFuncAttributeMaxDynamicSharedMemorySize, smem3);

    k0_prep<<<64, 256>>>((const float*)d_in[idx_lpw]);
    k1_stats<<<NPIX/256, 256>>>(x);
    k2_mix<<<dim3(Wn/T2, Hn/T2, Bn), NT2, smem2>>>(x);
    k3_final<<<dim3(Wn/T3W, Hn/T3H, Bn), NT3, smem3>>>((float*)d_out);
}

// round 10
// speedup vs baseline: 1.8735x; 1.1519x over previous
#include <cuda_runtime.h>
#include <cuda_bf16.h>
#include <stdint.h>
#include <math.h>

#define Bn 8
#define Cn 128
#define Hn 224
#define Wn 224
#define HWn (Hn*Wn)        // 50176
#define CHWn (Cn*HWn)      // 6422528
#define NPIX (Bn*HWn)      // 401408

// ---------------- scratch (static device globals; no allocation) ----------------
__device__ float g_y[(long long)Bn*CHWn];   // LN2-normalized, shuffled tensor (205.5 MB)
__device__ float g_m1[NPIX];
__device__ float g_r1[NPIX];
__device__ float g_spw_w[4*32*32];   // [g][o][c], group order (s2,s4,s1,s3)
__device__ float g_spw_wT[4*32*32];  // [g][c][o]  (filled by k0_prep)
__device__ float g_spw_b[128];
__device__ float g_c5w[128*9];
__device__ float g_c5b[128];
__device__ float g_n2w[128];
__device__ float g_n2b[128];
// final pw weights, bf16 hi/lo split, plain [o][ch] layout (filled by k0_prep)
__device__ __align__(16) unsigned short g_pwbh[Cn*Cn];
__device__ __align__(16) unsigned short g_pwbl[Cn*Cn];

// ---------------- constant weights (warp-uniform access only) ----------------
__constant__ float c_n1w[Cn], c_n1b[Cn];
__constant__ float c_sdw_w[4][32][9];
__constant__ float c_sdw_b[4][32];
__constant__ float c_ldww[Cn][9];
__constant__ float c_ldwb[Cn];
__constant__ float c_lpwb[Cn];

__device__ __forceinline__ float gelu_exact(float x) {
    return 0.5f * x * (1.0f + erff(x * 0.70710678118654752f));
}

// split fp32 -> bf16 hi + bf16 lo
__device__ __forceinline__ void bf16_split(float v, unsigned short& hb, unsigned short& lb) {
    __nv_bfloat16 h = __float2bfloat16(v);
    float hf = __bfloat162float(h);
    __nv_bfloat16 l = __float2bfloat16(v - hf);
    hb = *(unsigned short*)&h;
    lb = *(unsigned short*)&l;
}

// warp-level bf16 MMA (sm_80+ path, valid on base sm_100)
__device__ __forceinline__ void mma16816(float* c, const uint32_t* a, const uint32_t* b) {
    asm volatile(
        "mma.sync.aligned.m16n8k16.row.col.f32.bf16.bf16.f32 "
        "{%0,%1,%2,%3}, {%4,%5,%6,%7}, {%8,%9}, {%0,%1,%2,%3};"
        : "+f"(c[0]), "+f"(c[1]), "+f"(c[2]), "+f"(c[3])
        : "r"(a[0]), "r"(a[1]), "r"(a[2]), "r"(a[3]), "r"(b[0]), "r"(b[1]));
}

// ================= kernel 0: prep weights =================
__global__ __launch_bounds__(256) void k0_prep(const float* __restrict__ pw)
{
    int i = blockIdx.x * 256 + threadIdx.x;
    if (i < Cn*Cn) {
        unsigned short hb, lb;
        bf16_split(pw[i], hb, lb);
        g_pwbh[i] = hb;      // [o][ch] row-major
        g_pwbl[i] = lb;
    }
    if (i < 4096) {
        int g = i >> 10, r = i & 1023, o = r >> 5, c = r & 31;
        g_spw_wT[g*1024 + c*32 + o] = g_spw_w[i];
    }
}

// ================= kernel 1: LN1 stats =================
__global__ __launch_bounds__(256) void k1_stats(const float* __restrict__ x)
{
    int idx = blockIdx.x * 256 + threadIdx.x;
    int b  = idx / HWn;
    int hw = idx - b * HWn;
    const float* px = x + b * CHWn + hw;
    float s = 0.f, ss = 0.f;
    #pragma unroll 8
    for (int ch = 0; ch < Cn; ch++) {
        float v = px[ch * HWn];
        s += v; ss = fmaf(v, v, ss);
    }
    float m = s * (1.0f/128.0f);
    float var = fmaf(-m, m, ss * (1.0f/128.0f));
    g_m1[idx] = m;
    g_r1[idx] = rsqrtf(var + 1e-6f);
}

// ================= kernel 2: branches + c5 + shuffle + LN2 (unchanged from R6) =================
#define T2 8
#define R2 12
#define NT2 512
#define OFF_SX   0
#define OFF_ST   (OFF_SX + Cn*R2*R2)
#define OFF_W2   (OFF_ST + Cn*64)
#define OFF_RED  (OFF_W2 + 4096)
#define OFF_MS   (OFF_RED + 4096)
#define OFF_RS   (OFF_MS + 64)
#define OFF_GAM  (OFF_RS + 64)
#define OFF_BET  (OFF_GAM + 128)
#define OFF_C5W  (OFF_BET + 128)
#define OFF_C5B  (OFF_C5W + 1152)
#define OFF_PWB  (OFF_C5B + 128)
#define OFF_SM1  (OFF_PWB + 128)
#define OFF_SR1  (OFF_SM1 + 144)
#define SMEM2_FLOATS (OFF_SR1 + 144)

__global__ __launch_bounds__(NT2, 1) void k2_mix(const float* __restrict__ x)
{
    extern __shared__ float sm[];
    const int b  = blockIdx.z;
    const int h0 = blockIdx.y * T2;
    const int w0 = blockIdx.x * T2;
    const int tid = threadIdx.x;
    const int wid = tid >> 5, lane = tid & 31;
    const long long xb = (long long)b * CHWn;

    if (tid < 144) {
        int r = tid / 12, cc = tid - r * 12;
        int gh = h0 + r - 2, gw = w0 + cc - 2;
        float m = 0.f, rs = 0.f;
        if ((unsigned)gh < (unsigned)Hn && (unsigned)gw < (unsigned)Wn) {
            int p = b * HWn + gh * Wn + gw;
            m = g_m1[p]; rs = g_r1[p];
        }
        sm[OFF_SM1 + tid] = m; sm[OFF_SR1 + tid] = rs;
    }
    for (int i = tid; i < 4096; i += NT2) sm[OFF_W2 + i] = g_spw_wT[i];
    for (int i = tid; i < 1152; i += NT2) sm[OFF_C5W + i] = g_c5w[i];
    if (tid < 128) {
        sm[OFF_C5B + tid] = g_c5b[tid];
        sm[OFF_PWB + tid] = g_spw_b[tid];
        sm[OFF_GAM + tid] = g_n2w[tid];
        sm[OFF_BET + tid] = g_n2b[tid];
    }
    __syncthreads();

    for (int ch = wid; ch < Cn; ch += 16) {
        const float gam = c_n1w[ch], bet = c_n1b[ch];
        const float* xc = x + xb + (long long)ch * HWn;
        for (int pos = lane; pos < 144; pos += 32) {
            int r = pos / 12, cc = pos - r * 12;
            int gh = h0 + r - 2, gw = w0 + cc - 2;
            float v = 0.f;
            if ((unsigned)gh < (unsigned)Hn && (unsigned)gw < (unsigned)Wn)
                v = (xc[gh * Wn + gw] - sm[OFF_SM1 + pos]) * sm[OFF_SR1 + pos] * gam + bet;
            sm[OFF_SX + ch * 144 + pos] = v;
        }
    }
    __syncthreads();

    const int px  = tid & 63;
    const int py0 = px >> 3, px0 = px & 7;
    {
        const int h = h0 + py0, w = w0 + px0;
        bool my[3], mx[3];
        #pragma unroll
        for (int k = 0; k < 3; k++) {
            my[k] = (unsigned)(h + k - 1) < (unsigned)Hn;
            mx[k] = (unsigned)(w + k - 1) < (unsigned)Wn;
        }
        #pragma unroll 4
        for (int it = 0; it < 16; it++) {
            const int ch = (tid >> 6) + it * 8;
            const int gg = ch >> 5, cc = ch & 31;
            const int srcb = ((0x2031 >> (4*gg)) & 15) << 5;
            const int offy = (0x2002 >> (4*gg)) & 15;
            const int offx = (0x2020 >> (4*gg)) & 15;
            const float* bp = sm + OFF_SX + (srcb + cc) * 144 + (py0 + offy) * 12 + (px0 + offx);
            float a = c_sdw_b[gg][cc];
            #pragma unroll
            for (int dy = 0; dy < 3; dy++)
                #pragma unroll
                for (int dx = 0; dx < 3; dx++)
                    if (my[dy] && mx[dx])
                        a = fmaf(c_sdw_w[gg][cc][dy*3+dx], bp[dy*12+dx], a);
            sm[OFF_ST + ch * 64 + px] = gelu_exact(a);
        }
    }
    __syncthreads();

    const int o0 = (tid >> 4) * 4;
    const int q  = (tid & 15) * 4;
    const int g  = o0 >> 5, ol = o0 & 31;
    const int qy = q >> 3, qx = q & 7;

    float acc[4][4];
    #pragma unroll
    for (int j = 0; j < 4; j++) {
        float bj = sm[OFF_PWB + o0 + j];
        acc[j][0] = bj; acc[j][1] = bj; acc[j][2] = bj; acc[j][3] = bj;
    }
    {
        const float* w2g = sm + OFF_W2 + g * 1024 + ol;
        const float* stg = sm + OFF_ST + (g * 32) * 64 + q;
        #pragma unroll 8
        for (int c = 0; c < 32; c++) {
            float4 wa = *(const float4*)(w2g + c * 32);
            float4 tv = *(const float4*)(stg + c * 64);
            acc[0][0]=fmaf(wa.x,tv.x,acc[0][0]); acc[0][1]=fmaf(wa.x,tv.y,acc[0][1]); acc[0][2]=fmaf(wa.x,tv.z,acc[0][2]); acc[0][3]=fmaf(wa.x,tv.w,acc[0][3]);
            acc[1][0]=fmaf(wa.y,tv.x,acc[1][0]); acc[1][1]=fmaf(wa.y,tv.y,acc[1][1]); acc[1][2]=fmaf(wa.y,tv.z,acc[1][2]); acc[1][3]=fmaf(wa.y,tv.w,acc[1][3]);
            acc[2][0]=fmaf(wa.z,tv.x,acc[2][0]); acc[2][1]=fmaf(wa.z,tv.y,acc[2][1]); acc[2][2]=fmaf(wa.z,tv.z,acc[2][2]); acc[2][3]=fmaf(wa.z,tv.w,acc[2][3]);
            acc[3][0]=fmaf(wa.w,tv.x,acc[3][0]); acc[3][1]=fmaf(wa.w,tv.y,acc[3][1]); acc[3][2]=fmaf(wa.w,tv.z,acc[3][2]); acc[3][3]=fmaf(wa.w,tv.w,acc[3][3]);
        }
    }
    #pragma unroll
    for (int j = 0; j < 4; j++) {
        const int ci = o0 + j;
        const float* cw = sm + OFF_C5W + ci * 9;
        const float* bp = sm + OFF_SX + ci * 144 + (qy + 1) * 12 + (qx + 1);
        const float b5 = sm[OFF_C5B + ci];
        #pragma unroll
        for (int i = 0; i < 4; i++) {
            float a5 = b5;
            #pragma unroll
            for (int k = 0; k < 9; k++)
                a5 = fmaf(cw[k], bp[(k/3)*12 + (k%3) + i], a5);
            acc[j][i] += a5;
        }
    }
    {
        float ps[4] = {0,0,0,0}, pq[4] = {0,0,0,0};
        #pragma unroll
        for (int j = 0; j < 4; j++)
            #pragma unroll
            for (int i = 0; i < 4; i++) { ps[i] += acc[j][i]; pq[i] = fmaf(acc[j][i], acc[j][i], pq[i]); }
        #pragma unroll
        for (int i = 0; i < 4; i++) {
            sm[OFF_RED + (tid >> 4) * 64 + q + i]        = ps[i];
            sm[OFF_RED + 2048 + (tid >> 4) * 64 + q + i] = pq[i];
        }
    }
    __syncthreads();
    if (tid < 64) {
        float s = 0.f, ss = 0.f;
        #pragma unroll
        for (int r = 0; r < 32; r++) {
            s  += sm[OFF_RED + r * 64 + tid];
            ss += sm[OFF_RED + 2048 + r * 64 + tid];
        }
        float m = s * (1.0f/128.0f);
        float var = fmaf(-m, m, ss * (1.0f/128.0f));
        sm[OFF_MS + tid] = m;
        sm[OFF_RS + tid] = rsqrtf(var + 1e-6f);
    }
    __syncthreads();

    float mv[4], rv[4];
    #pragma unroll
    for (int i = 0; i < 4; i++) { mv[i] = sm[OFF_MS + q + i]; rv[i] = sm[OFF_RS + q + i]; }
    const long long obase = xb + (long long)(h0 + qy) * Wn + (w0 + qx);
    #pragma unroll
    for (int j = 0; j < 4; j++) {
        const int ci = o0 + j;
        const int ko = ((ci & 63) << 1) | (ci >> 6);
        const float gam = sm[OFF_GAM + ko], bet = sm[OFF_BET + ko];
        float4 ov;
        ov.x = fmaf((acc[j][0] - mv[0]) * rv[0], gam, bet);
        ov.y = fmaf((acc[j][1] - mv[1]) * rv[1], gam, bet);
        ov.z = fmaf((acc[j][2] - mv[2]) * rv[2], gam, bet);
        ov.w = fmaf((acc[j][3] - mv[3]) * rv[3], gam, bet);
        *(float4*)&g_y[obase + (long long)ko * HWn] = ov;
    }
}

// ================= kernel 3: dw3(gelu) + mma.sync bf16-split GEMM =================
// tile 16w x 8h = 128 px; M=128(px) N=128(o) K=128(ch); 512 threads = 16 warps.
// Each warp owns a 32x32 output tile (4x4 grid of warps), via m16n8k16 fragments.
#define T3W 16
#define T3H 8
#define R3H 10
#define R3W 18
#define NT3 512
#define AS3 136                        // bf16 row stride (272B): conflict-free frags
// smem byte offsets
#define SM3_AH   0
#define SM3_AL   (SM3_AH + 128*AS3*2)   // 34816
#define SM3_BH   (SM3_AL + 128*AS3*2)   // 69632
#define SM3_BL   (SM3_BH + 128*AS3*2)   // 104448
#define SM3_Y    (SM3_BL + 128*AS3*2)   // 139264
#define SM3_BIAS (SM3_Y + 64*R3H*R3W*4) // 185344
#define SM3_TOTAL (SM3_BIAS + 512)      // 185856 bytes

__global__ __launch_bounds__(NT3, 1) void k3_final(float* __restrict__ out)
{
    extern __shared__ char smc[];
    float* ysm  = (float*)(smc + SM3_Y);
    float* bias = (float*)(smc + SM3_BIAS);
    const int b  = blockIdx.z;
    const int h0 = blockIdx.y * T3H;
    const int w0 = blockIdx.x * T3W;
    const int tid = threadIdx.x;
    const int wid = tid >> 5, lane = tid & 31;
    const long long xb = (long long)b * CHWn;

    // stage B hi/lo into [o][AS3] bf16 (uint2 = 4 bf16 chunks; 272 % 8 == 0)
    for (int i = tid; i < 4096; i += NT3) {
        int o = i >> 5, qq = i & 31;
        *(uint2*)(smc + SM3_BH + o * (AS3*2) + qq * 8) = ((const uint2*)g_pwbh)[i];
        *(uint2*)(smc + SM3_BL + o * (AS3*2) + qq * 8) = ((const uint2*)g_pwbl)[i];
    }
    if (tid < 128) bias[tid] = c_lpwb[tid];

    // two channel halves: stage y tile -> dw3+gelu -> A_hi/A_lo bf16 [px][AS3]
    for (int h2 = 0; h2 < 2; h2++) {
        __syncthreads();
        for (int i = tid; i < 64 * R3H * R3W; i += NT3) {
            int ch = i / (R3H * R3W);
            int pos = i - ch * (R3H * R3W);
            int r = pos / R3W, cc = pos - r * R3W;
            int gh = h0 + r - 1, gw = w0 + cc - 1;
            float v = 0.f;
            if ((unsigned)gh < (unsigned)Hn && (unsigned)gw < (unsigned)Wn)
                v = g_y[xb + (long long)(h2 * 64 + ch) * HWn + gh * Wn + gw];
            ysm[i] = v;
        }
        __syncthreads();
        for (int i = tid; i < 64 * 128; i += NT3) {
            int chl = i >> 7, p = i & 127;        // chl warp-uniform
            int ch = h2 * 64 + chl;
            int py = p >> 4, pxx = p & 15;
            const float* bp = ysm + chl * (R3H * R3W) + py * R3W + pxx;
            float a = c_ldwb[ch];
            #pragma unroll
            for (int k = 0; k < 9; k++)
                a = fmaf(c_ldww[ch][k], bp[(k/3)*R3W + (k%3)], a);
            float v = gelu_exact(a);
            unsigned short hb, lb;
            bf16_split(v, hb, lb);
            *(unsigned short*)(smc + SM3_AH + p * (AS3*2) + ch * 2) = hb;
            *(unsigned short*)(smc + SM3_AL + p * (AS3*2) + ch * 2) = lb;
        }
    }
    __syncthreads();

    // warp GEMM: 3 passes (AhBh, AhBl, AlBh) accumulated in fp32 fragments
    const int mi = wid >> 2, ni = wid & 3;
    const int lr = lane >> 2, lc = lane & 3;     // group row / quad col
    float cfr[8][4];
    #pragma unroll
    for (int t = 0; t < 8; t++) { cfr[t][0]=0.f; cfr[t][1]=0.f; cfr[t][2]=0.f; cfr[t][3]=0.f; }

    #pragma unroll
    for (int pass = 0; pass < 3; pass++) {
        const char* Ab = smc + (pass == 2 ? SM3_AL : SM3_AH);
        const char* Bb = smc + (pass == 1 ? SM3_BL : SM3_BH);
        #pragma unroll
        for (int k0 = 0; k0 < 8; k0++) {
            const int kb = k0 * 16;              // k column base (bf16)
            uint32_t a[2][4], bfr[4][2];
            #pragma unroll
            for (int m2 = 0; m2 < 2; m2++) {
                const char* ap = Ab + (mi*32 + m2*16 + lr) * (AS3*2) + (kb + lc*2) * 2;
                a[m2][0] = *(const uint32_t*)(ap);
                a[m2][1] = *(const uint32_t*)(ap + 8 * (AS3*2));
                a[m2][2] = *(const uint32_t*)(ap + 16);
                a[m2][3] = *(const uint32_t*)(ap + 8 * (AS3*2) + 16);
            }
            #pragma unroll
            for (int n4 = 0; n4 < 4; n4++) {
                const char* bp = Bb + (ni*32 + n4*8 + lr) * (AS3*2) + (kb + lc*2) * 2;
                bfr[n4][0] = *(const uint32_t*)(bp);
                bfr[n4][1] = *(const uint32_t*)(bp + 16);
            }
            #pragma unroll
            for (int m2 = 0; m2 < 2; m2++)
                #pragma unroll
                for (int n4 = 0; n4 < 4; n4++)
                    mma16816(cfr[m2*4 + n4], a[m2], bfr[n4]);
        }
    }

    // epilogue: add bias, store direct to gmem (32B-aligned sectors)
    #pragma unroll
    for (int m2 = 0; m2 < 2; m2++) {
        #pragma unroll
        for (int n4 = 0; n4 < 4; n4++) {
            const float* cf = cfr[m2*4 + n4];
            const int p0 = mi*32 + m2*16 + lr;
            const int p1 = p0 + 8;
            const int oo = ni*32 + n4*8 + lc*2;
            const float b0v = bias[oo], b1v = bias[oo + 1];
            const long long r0 = xb + (long long)(h0 + (p0 >> 4)) * Wn + (w0 + (p0 & 15));
            const long long r1 = xb + (long long)(h0 + (p1 >> 4)) * Wn + (w0 + (p1 & 15));
            out[r0 + (long long)oo * HWn]       = cf[0] + b0v;
            out[r0 + (long long)(oo+1) * HWn]   = cf[1] + b1v;
            out[r1 + (long long)oo * HWn]       = cf[2] + b0v;
            out[r1 + (long long)(oo+1) * HWn]   = cf[3] + b1v;
        }
    }
}

// ================= launch =================
extern "C" void kernel_launch(void* const* d_in, const int* in_sizes, int n_in,
                              void* d_out, int out_size)
{
    (void)out_size;
    int idx_x = 0, idx_lpw = -1, idx_c5w = -1, idx_ldww = -1;
    int dw_w[4] = {-1,-1,-1,-1}, pw_w[4] = {-1,-1,-1,-1};
    int ndw = 0, npw = 0;
    for (int i = 0; i < n_in; i++) {
        int s = in_sizes[i];
        if (s > 100000)      idx_x = i;
        else if (s == 16384) idx_lpw = i;
        else if (s == 1152)  { if (idx_c5w < 0) idx_c5w = i; else idx_ldww = i; }
        else if (s == 288 && ndw < 4)  dw_w[ndw++] = i;
        else if (s == 1024 && npw < 4) pw_w[npw++] = i;
    }
    const int idx_c5b  = idx_c5w  + 1;
    const int idx_ldwb = idx_ldww + 1;
    const int idx_lpwb = idx_lpw  + 1;
    int v128[8]; int nv = 0;
    for (int i = 0; i < n_in; i++)
        if (in_sizes[i] == 128 && i != idx_c5b && i != idx_ldwb && i != idx_lpwb && nv < 8)
            v128[nv++] = i;
    const int idx_n1w = v128[0], idx_n1b = v128[1];
    const int idx_n2w = v128[2], idx_n2b = v128[3];

    const float* x = (const float*)d_in[idx_x];

    cudaMemcpyToSymbolAsync(c_n1w, d_in[idx_n1w], Cn*4, 0, cudaMemcpyDeviceToDevice);
    cudaMemcpyToSymbolAsync(c_n1b, d_in[idx_n1b], Cn*4, 0, cudaMemcpyDeviceToDevice);
    const int GS[4] = {1, 3, 0, 2};
    for (int g = 0; g < 4; g++) {
        int sbx = GS[g];
        cudaMemcpyToSymbolAsync(c_sdw_w,  d_in[dw_w[sbx]],     32*9*4,  g*32*9*4,  cudaMemcpyDeviceToDevice);
        cudaMemcpyToSymbolAsync(c_sdw_b,  d_in[dw_w[sbx] + 1], 32*4,    g*32*4,    cudaMemcpyDeviceToDevice);
        cudaMemcpyToSymbolAsync(g_spw_w,  d_in[pw_w[sbx]],     32*32*4, g*32*32*4, cudaMemcpyDeviceToDevice);
        cudaMemcpyToSymbolAsync(g_spw_b,  d_in[pw_w[sbx] + 1], 32*4,    g*32*4,    cudaMemcpyDeviceToDevice);
    }
    cudaMemcpyToSymbolAsync(g_c5w,  d_in[idx_c5w],  Cn*9*4, 0, cudaMemcpyDeviceToDevice);
    cudaMemcpyToSymbolAsync(g_c5b,  d_in[idx_c5b],  Cn*4,   0, cudaMemcpyDeviceToDevice);
    cudaMemcpyToSymbolAsync(g_n2w,  d_in[idx_n2w],  Cn*4,   0, cudaMemcpyDeviceToDevice);
    cudaMemcpyToSymbolAsync(g_n2b,  d_in[idx_n2b],  Cn*4,   0, cudaMemcpyDeviceToDevice);
    cudaMemcpyToSymbolAsync(c_ldww, d_in[idx_ldww], Cn*9*4, 0, cudaMemcpyDeviceToDevice);
    cudaMemcpyToSymbolAsync(c_ldwb, d_in[idx_ldwb], Cn*4,   0, cudaMemcpyDeviceToDevice);
    cudaMemcpyToSymbolAsync(c_lpwb, d_in[idx_lpwb], Cn*4,   0, cudaMemcpyDeviceToDevice);

    const int smem2 = SMEM2_FLOATS * 4;
    cudaFuncSetAttribute(k2_mix,   cudaFuncAttributeMaxDynamicSharedMemorySize, smem2);
    cudaFuncSetAttribute(k3_final, cudaFuncAttributeMaxDynamicSharedMemorySize, SM3_TOTAL);

    k0_prep<<<64, 256>>>((const float*)d_in[idx_lpw]);
    k1_stats<<<NPIX/256, 256>>>(x);
    k2_mix<<<dim3(Wn/T2, Hn/T2, Bn), NT2, smem2>>>(x);
    k3_final<<<dim3(Wn/T3W, Hn/T3H, Bn), NT3, SM3_TOTAL>>>((float*)d_out);
}

// round 11
// speedup vs baseline: 1.8795x; 1.0032x over previous
#include <cuda_runtime.h>
#include <cuda_bf16.h>
#include <stdint.h>
#include <math.h>

#define Bn 8
#define Cn 128
#define Hn 224
#define Wn 224
#define HWn (Hn*Wn)        // 50176
#define CHWn (Cn*HWn)      // 6422528
#define NPIX (Bn*HWn)      // 401408

// ---------------- scratch (static device globals; no allocation) ----------------
__device__ float g_y[(long long)Bn*CHWn];   // LN2-normalized, shuffled tensor (205.5 MB)
__device__ float g_m1[NPIX];
__device__ float g_r1[NPIX];
__device__ float g_spw_w[4*32*32];   // [g][o][c], group order (s2,s4,s1,s3)
__device__ float g_spw_wT[4*32*32];  // [g][c][o]  (filled by k0_prep)
__device__ float g_spw_b[128];
__device__ float g_c5w[128*9];
__device__ float g_c5b[128];
__device__ float g_n2w[128];
__device__ float g_n2b[128];
// final pw weights, bf16 hi/lo split, plain [o][ch] layout (filled by k0_prep)
__device__ __align__(16) unsigned short g_pwbh[Cn*Cn];
__device__ __align__(16) unsigned short g_pwbl[Cn*Cn];

// ---------------- constant weights (warp-uniform access only) ----------------
__constant__ float c_n1w[Cn], c_n1b[Cn];
__constant__ float c_sdw_w[4][32][9];
__constant__ float c_sdw_b[4][32];
__constant__ float c_ldww[Cn][9];
__constant__ float c_ldwb[Cn];
__constant__ float c_lpwb[Cn];

__device__ __forceinline__ float gelu_exact(float x) {
    return 0.5f * x * (1.0f + erff(x * 0.70710678118654752f));
}

// split fp32 -> bf16 hi + bf16 lo
__device__ __forceinline__ void bf16_split(float v, unsigned short& hb, unsigned short& lb) {
    __nv_bfloat16 h = __float2bfloat16(v);
    float hf = __bfloat162float(h);
    __nv_bfloat16 l = __float2bfloat16(v - hf);
    hb = *(unsigned short*)&h;
    lb = *(unsigned short*)&l;
}

// warp-level bf16 MMA (sm_80+ path, valid on base sm_100)
__device__ __forceinline__ void mma16816(float* c, const uint32_t* a, const uint32_t* b) {
    asm volatile(
        "mma.sync.aligned.m16n8k16.row.col.f32.bf16.bf16.f32 "
        "{%0,%1,%2,%3}, {%4,%5,%6,%7}, {%8,%9}, {%0,%1,%2,%3};"
        : "+f"(c[0]), "+f"(c[1]), "+f"(c[2]), "+f"(c[3])
        : "r"(a[0]), "r"(a[1]), "r"(a[2]), "r"(a[3]), "r"(b[0]), "r"(b[1]));
}

// ================= kernel 0: prep weights =================
__global__ __launch_bounds__(256) void k0_prep(const float* __restrict__ pw)
{
    int i = blockIdx.x * 256 + threadIdx.x;
    if (i < Cn*Cn) {
        unsigned short hb, lb;
        bf16_split(pw[i], hb, lb);
        g_pwbh[i] = hb;      // [o][ch] row-major
        g_pwbl[i] = lb;
    }
    if (i < 4096) {
        int g = i >> 10, r = i & 1023, o = r >> 5, c = r & 31;
        g_spw_wT[g*1024 + c*32 + o] = g_spw_w[i];
    }
}

// ================= kernel 1: LN1 stats =================
__global__ __launch_bounds__(256) void k1_stats(const float* __restrict__ x)
{
    int idx = blockIdx.x * 256 + threadIdx.x;
    int b  = idx / HWn;
    int hw = idx - b * HWn;
    const float* px = x + b * CHWn + hw;
    float s = 0.f, ss = 0.f;
    #pragma unroll 8
    for (int ch = 0; ch < Cn; ch++) {
        float v = px[ch * HWn];
        s += v; ss = fmaf(v, v, ss);
    }
    float m = s * (1.0f/128.0f);
    float var = fmaf(-m, m, ss * (1.0f/128.0f));
    g_m1[idx] = m;
    g_r1[idx] = rsqrtf(var + 1e-6f);
}

// ================= kernel 2: branches + c5 + shuffle + LN2 (unchanged from R6) =================
#define T2 8
#define R2 12
#define NT2 512
#define OFF_SX   0
#define OFF_ST   (OFF_SX + Cn*R2*R2)
#define OFF_W2   (OFF_ST + Cn*64)
#define OFF_RED  (OFF_W2 + 4096)
#define OFF_MS   (OFF_RED + 4096)
#define OFF_RS   (OFF_MS + 64)
#define OFF_GAM  (OFF_RS + 64)
#define OFF_BET  (OFF_GAM + 128)
#define OFF_C5W  (OFF_BET + 128)
#define OFF_C5B  (OFF_C5W + 1152)
#define OFF_PWB  (OFF_C5B + 128)
#define OFF_SM1  (OFF_PWB + 128)
#define OFF_SR1  (OFF_SM1 + 144)
#define SMEM2_FLOATS (OFF_SR1 + 144)

__global__ __launch_bounds__(NT2, 1) void k2_mix(const float* __restrict__ x)
{
    extern __shared__ float sm[];
    const int b  = blockIdx.z;
    const int h0 = blockIdx.y * T2;
    const int w0 = blockIdx.x * T2;
    const int tid = threadIdx.x;
    const int wid = tid >> 5, lane = tid & 31;
    const long long xb = (long long)b * CHWn;

    if (tid < 144) {
        int r = tid / 12, cc = tid - r * 12;
        int gh = h0 + r - 2, gw = w0 + cc - 2;
        float m = 0.f, rs = 0.f;
        if ((unsigned)gh < (unsigned)Hn && (unsigned)gw < (unsigned)Wn) {
            int p = b * HWn + gh * Wn + gw;
            m = g_m1[p]; rs = g_r1[p];
        }
        sm[OFF_SM1 + tid] = m; sm[OFF_SR1 + tid] = rs;
    }
    for (int i = tid; i < 4096; i += NT2) sm[OFF_W2 + i] = g_spw_wT[i];
    for (int i = tid; i < 1152; i += NT2) sm[OFF_C5W + i] = g_c5w[i];
    if (tid < 128) {
        sm[OFF_C5B + tid] = g_c5b[tid];
        sm[OFF_PWB + tid] = g_spw_b[tid];
        sm[OFF_GAM + tid] = g_n2w[tid];
        sm[OFF_BET + tid] = g_n2b[tid];
    }
    __syncthreads();

    for (int ch = wid; ch < Cn; ch += 16) {
        const float gam = c_n1w[ch], bet = c_n1b[ch];
        const float* xc = x + xb + (long long)ch * HWn;
        for (int pos = lane; pos < 144; pos += 32) {
            int r = pos / 12, cc = pos - r * 12;
            int gh = h0 + r - 2, gw = w0 + cc - 2;
            float v = 0.f;
            if ((unsigned)gh < (unsigned)Hn && (unsigned)gw < (unsigned)Wn)
                v = (xc[gh * Wn + gw] - sm[OFF_SM1 + pos]) * sm[OFF_SR1 + pos] * gam + bet;
            sm[OFF_SX + ch * 144 + pos] = v;
        }
    }
    __syncthreads();

    const int px  = tid & 63;
    const int py0 = px >> 3, px0 = px & 7;
    {
        const int h = h0 + py0, w = w0 + px0;
        bool my[3], mx[3];
        #pragma unroll
        for (int k = 0; k < 3; k++) {
            my[k] = (unsigned)(h + k - 1) < (unsigned)Hn;
            mx[k] = (unsigned)(w + k - 1) < (unsigned)Wn;
        }
        #pragma unroll 4
        for (int it = 0; it < 16; it++) {
            const int ch = (tid >> 6) + it * 8;
            const int gg = ch >> 5, cc = ch & 31;
            const int srcb = ((0x2031 >> (4*gg)) & 15) << 5;
            const int offy = (0x2002 >> (4*gg)) & 15;
            const int offx = (0x2020 >> (4*gg)) & 15;
            const float* bp = sm + OFF_SX + (srcb + cc) * 144 + (py0 + offy) * 12 + (px0 + offx);
            float a = c_sdw_b[gg][cc];
            #pragma unroll
            for (int dy = 0; dy < 3; dy++)
                #pragma unroll
                for (int dx = 0; dx < 3; dx++)
                    if (my[dy] && mx[dx])
                        a = fmaf(c_sdw_w[gg][cc][dy*3+dx], bp[dy*12+dx], a);
            sm[OFF_ST + ch * 64 + px] = gelu_exact(a);
        }
    }
    __syncthreads();

    const int o0 = (tid >> 4) * 4;
    const int q  = (tid & 15) * 4;
    const int g  = o0 >> 5, ol = o0 & 31;
    const int qy = q >> 3, qx = q & 7;

    float acc[4][4];
    #pragma unroll
    for (int j = 0; j < 4; j++) {
        float bj = sm[OFF_PWB + o0 + j];
        acc[j][0] = bj; acc[j][1] = bj; acc[j][2] = bj; acc[j][3] = bj;
    }
    {
        const float* w2g = sm + OFF_W2 + g * 1024 + ol;
        const float* stg = sm + OFF_ST + (g * 32) * 64 + q;
        #pragma unroll 8
        for (int c = 0; c < 32; c++) {
            float4 wa = *(const float4*)(w2g + c * 32);
            float4 tv = *(const float4*)(stg + c * 64);
            acc[0][0]=fmaf(wa.x,tv.x,acc[0][0]); acc[0][1]=fmaf(wa.x,tv.y,acc[0][1]); acc[0][2]=fmaf(wa.x,tv.z,acc[0][2]); acc[0][3]=fmaf(wa.x,tv.w,acc[0][3]);
            acc[1][0]=fmaf(wa.y,tv.x,acc[1][0]); acc[1][1]=fmaf(wa.y,tv.y,acc[1][1]); acc[1][2]=fmaf(wa.y,tv.z,acc[1][2]); acc[1][3]=fmaf(wa.y,tv.w,acc[1][3]);
            acc[2][0]=fmaf(wa.z,tv.x,acc[2][0]); acc[2][1]=fmaf(wa.z,tv.y,acc[2][1]); acc[2][2]=fmaf(wa.z,tv.z,acc[2][2]); acc[2][3]=fmaf(wa.z,tv.w,acc[2][3]);
            acc[3][0]=fmaf(wa.w,tv.x,acc[3][0]); acc[3][1]=fmaf(wa.w,tv.y,acc[3][1]); acc[3][2]=fmaf(wa.w,tv.z,acc[3][2]); acc[3][3]=fmaf(wa.w,tv.w,acc[3][3]);
        }
    }
    #pragma unroll
    for (int j = 0; j < 4; j++) {
        const int ci = o0 + j;
        const float* cw = sm + OFF_C5W + ci * 9;
        const float* bp = sm + OFF_SX + ci * 144 + (qy + 1) * 12 + (qx + 1);
        const float b5 = sm[OFF_C5B + ci];
        #pragma unroll
        for (int i = 0; i < 4; i++) {
            float a5 = b5;
            #pragma unroll
            for (int k = 0; k < 9; k++)
                a5 = fmaf(cw[k], bp[(k/3)*12 + (k%3) + i], a5);
            acc[j][i] += a5;
        }
    }
    {
        float ps[4] = {0,0,0,0}, pq[4] = {0,0,0,0};
        #pragma unroll
        for (int j = 0; j < 4; j++)
            #pragma unroll
            for (int i = 0; i < 4; i++) { ps[i] += acc[j][i]; pq[i] = fmaf(acc[j][i], acc[j][i], pq[i]); }
        #pragma unroll
        for (int i = 0; i < 4; i++) {
            sm[OFF_RED + (tid >> 4) * 64 + q + i]        = ps[i];
            sm[OFF_RED + 2048 + (tid >> 4) * 64 + q + i] = pq[i];
        }
    }
    __syncthreads();
    if (tid < 64) {
        float s = 0.f, ss = 0.f;
        #pragma unroll
        for (int r = 0; r < 32; r++) {
            s  += sm[OFF_RED + r * 64 + tid];
            ss += sm[OFF_RED + 2048 + r * 64 + tid];
        }
        float m = s * (1.0f/128.0f);
        float var = fmaf(-m, m, ss * (1.0f/128.0f));
        sm[OFF_MS + tid] = m;
        sm[OFF_RS + tid] = rsqrtf(var + 1e-6f);
    }
    __syncthreads();

    float mv[4], rv[4];
    #pragma unroll
    for (int i = 0; i < 4; i++) { mv[i] = sm[OFF_MS + q + i]; rv[i] = sm[OFF_RS + q + i]; }
    const long long obase = xb + (long long)(h0 + qy) * Wn + (w0 + qx);
    #pragma unroll
    for (int j = 0; j < 4; j++) {
        const int ci = o0 + j;
        const int ko = ((ci & 63) << 1) | (ci >> 6);
        const float gam = sm[OFF_GAM + ko], bet = sm[OFF_BET + ko];
        float4 ov;
        ov.x = fmaf((acc[j][0] - mv[0]) * rv[0], gam, bet);
        ov.y = fmaf((acc[j][1] - mv[1]) * rv[1], gam, bet);
        ov.z = fmaf((acc[j][2] - mv[2]) * rv[2], gam, bet);
        ov.w = fmaf((acc[j][3] - mv[3]) * rv[3], gam, bet);
        *(float4*)&g_y[obase + (long long)ko * HWn] = ov;
    }
}

// ================= kernel 3: dw3(gelu) + mma.sync bf16-split GEMM =================
// tile 16w x 8h = 128 px; M=128(px) N=128(o) K=128(ch); 512 threads = 16 warps.
// Each warp owns a 32x32 output tile (4x4 grid of warps), via m16n8k16 fragments.
#define T3W 16
#define T3H 8
#define R3H 10
#define R3W 18
#define NT3 512
#define AS3 136                        // bf16 row stride (272B): conflict-free frags
// smem byte offsets
#define SM3_AH   0
#define SM3_AL   (SM3_AH + 128*AS3*2)   // 34816
#define SM3_BH   (SM3_AL + 128*AS3*2)   // 69632
#define SM3_BL   (SM3_BH + 128*AS3*2)   // 104448
#define SM3_Y    (SM3_BL + 128*AS3*2)   // 139264
#define SM3_BIAS (SM3_Y + 64*R3H*R3W*4) // 185344
#define SM3_TOTAL (SM3_BIAS + 512)      // 185856 bytes

__global__ __launch_bounds__(NT3, 1) void k3_final(float* __restrict__ out)
{
    extern __shared__ char smc[];
    float* ysm  = (float*)(smc + SM3_Y);
    float* bias = (float*)(smc + SM3_BIAS);
    const int b  = blockIdx.z;
    const int h0 = blockIdx.y * T3H;
    const int w0 = blockIdx.x * T3W;
    const int tid = threadIdx.x;
    const int wid = tid >> 5, lane = tid & 31;
    const long long xb = (long long)b * CHWn;

    // stage B hi/lo into [o][AS3] bf16 (uint2 = 4 bf16 chunks; 272 % 8 == 0)
    for (int i = tid; i < 4096; i += NT3) {
        int o = i >> 5, qq = i & 31;
        *(uint2*)(smc + SM3_BH + o * (AS3*2) + qq * 8) = ((const uint2*)g_pwbh)[i];
        *(uint2*)(smc + SM3_BL + o * (AS3*2) + qq * 8) = ((const uint2*)g_pwbl)[i];
    }
    if (tid < 128) bias[tid] = c_lpwb[tid];

    // two channel halves: stage y tile -> dw3+gelu -> A_hi/A_lo bf16 [px][AS3]
    for (int h2 = 0; h2 < 2; h2++) {
        __syncthreads();
        for (int i = tid; i < 64 * R3H * R3W; i += NT3) {
            int ch = i / (R3H * R3W);
            int pos = i - ch * (R3H * R3W);
            int r = pos / R3W, cc = pos - r * R3W;
            int gh = h0 + r - 1, gw = w0 + cc - 1;
            float v = 0.f;
            if ((unsigned)gh < (unsigned)Hn && (unsigned)gw < (unsigned)Wn)
                v = g_y[xb + (long long)(h2 * 64 + ch) * HWn + gh * Wn + gw];
            ysm[i] = v;
        }
        __syncthreads();
        for (int i = tid; i < 64 * 128; i += NT3) {
            int chl = i >> 7, p = i & 127;        // chl warp-uniform
            int ch = h2 * 64 + chl;
            int py = p >> 4, pxx = p & 15;
            const float* bp = ysm + chl * (R3H * R3W) + py * R3W + pxx;
            float a = c_ldwb[ch];
            #pragma unroll
            for (int k = 0; k < 9; k++)
                a = fmaf(c_ldww[ch][k], bp[(k/3)*R3W + (k%3)], a);
            float v = gelu_exact(a);
            unsigned short hb, lb;
            bf16_split(v, hb, lb);
            *(unsigned short*)(smc + SM3_AH + p * (AS3*2) + ch * 2) = hb;
            *(unsigned short*)(smc + SM3_AL + p * (AS3*2) + ch * 2) = lb;
        }
    }
    __syncthreads();

    // warp GEMM: 3 passes (AhBh, AhBl, AlBh) accumulated in fp32 fragments
    const int mi = wid >> 2, ni = wid & 3;
    const int lr = lane >> 2, lc = lane & 3;     // group row / quad col
    float cfr[8][4];
    #pragma unroll
    for (int t = 0; t < 8; t++) { cfr[t][0]=0.f; cfr[t][1]=0.f; cfr[t][2]=0.f; cfr[t][3]=0.f; }

    #pragma unroll
    for (int pass = 0; pass < 3; pass++) {
        const char* Ab = smc + (pass == 2 ? SM3_AL : SM3_AH);
        const char* Bb = smc + (pass == 1 ? SM3_BL : SM3_BH);
        #pragma unroll
        for (int k0 = 0; k0 < 8; k0++) {
            const int kb = k0 * 16;              // k column base (bf16)
            uint32_t a[2][4], bfr[4][2];
            #pragma unroll
            for (int m2 = 0; m2 < 2; m2++) {
                const char* ap = Ab + (mi*32 + m2*16 + lr) * (AS3*2) + (kb + lc*2) * 2;
                a[m2][0] = *(const uint32_t*)(ap);
                a[m2][1] = *(const uint32_t*)(ap + 8 * (AS3*2));
                a[m2][2] = *(const uint32_t*)(ap + 16);
                a[m2][3] = *(const uint32_t*)(ap + 8 * (AS3*2) + 16);
            }
            #pragma unroll
            for (int n4 = 0; n4 < 4; n4++) {
                const char* bp = Bb + (ni*32 + n4*8 + lr) * (AS3*2) + (kb + lc*2) * 2;
                bfr[n4][0] = *(const uint32_t*)(bp);
                bfr[n4][1] = *(const uint32_t*)(bp + 16);
            }
            #pragma unroll
            for (int m2 = 0; m2 < 2; m2++)
                #pragma unroll
                for (int n4 = 0; n4 < 4; n4++)
                    mma16816(cfr[m2*4 + n4], a[m2], bfr[n4]);
        }
    }

    // epilogue: add bias, store direct to gmem (32B-aligned sectors)
    #pragma unroll
    for (int m2 = 0; m2 < 2; m2++) {
        #pragma unroll
        for (int n4 = 0; n4 < 4; n4++) {
            const float* cf = cfr[m2*4 + n4];
            const int p0 = mi*32 + m2*16 + lr;
            const int p1 = p0 + 8;
            const int oo = ni*32 + n4*8 + lc*2;
            const float b0v = bias[oo], b1v = bias[oo + 1];
            const long long r0 = xb + (long long)(h0 + (p0 >> 4)) * Wn + (w0 + (p0 & 15));
            const long long r1 = xb + (long long)(h0 + (p1 >> 4)) * Wn + (w0 + (p1 & 15));
            out[r0 + (long long)oo * HWn]       = cf[0] + b0v;
            out[r0 + (long long)(oo+1) * HWn]   = cf[1] + b1v;
            out[r1 + (long long)oo * HWn]       = cf[2] + b0v;
            out[r1 + (long long)(oo+1) * HWn]   = cf[3] + b1v;
        }
    }
}

// ================= launch =================
extern "C" void kernel_launch(void* const* d_in, const int* in_sizes, int n_in,
                              void* d_out, int out_size)
{
    (void)out_size;
    int idx_x = 0, idx_lpw = -1, idx_c5w = -1, idx_ldww = -1;
    int dw_w[4] = {-1,-1,-1,-1}, pw_w[4] = {-1,-1,-1,-1};
    int ndw = 0, npw = 0;
    for (int i = 0; i < n_in; i++) {
        int s = in_sizes[i];
        if (s > 100000)      idx_x = i;
        else if (s == 16384) idx_lpw = i;
        else if (s == 1152)  { if (idx_c5w < 0) idx_c5w = i; else idx_ldww = i; }
        else if (s == 288 && ndw < 4)  dw_w[ndw++] = i;
        else if (s == 1024 && npw < 4) pw_w[npw++] = i;
    }
    const int idx_c5b  = idx_c5w  + 1;
    const int idx_ldwb = idx_ldww + 1;
    const int idx_lpwb = idx_lpw  + 1;
    int v128[8]; int nv = 0;
    for (int i = 0; i < n_in; i++)
        if (in_sizes[i] == 128 && i != idx_c5b && i != idx_ldwb && i != idx_lpwb && nv < 8)
            v128[nv++] = i;
    const int idx_n1w = v128[0], idx_n1b = v128[1];
    const int idx_n2w = v128[2], idx_n2b = v128[3];

    const float* x = (const float*)d_in[idx_x];

    cudaMemcpyToSymbolAsync(c_n1w, d_in[idx_n1w], Cn*4, 0, cudaMemcpyDeviceToDevice);
    cudaMemcpyToSymbolAsync(c_n1b, d_in[idx_n1b], Cn*4, 0, cudaMemcpyDeviceToDevice);
    const int GS[4] = {1, 3, 0, 2};
    for (int g = 0; g < 4; g++) {
        int sbx = GS[g];
        cudaMemcpyToSymbolAsync(c_sdw_w,  d_in[dw_w[sbx]],     32*9*4,  g*32*9*4,  cudaMemcpyDeviceToDevice);
        cudaMemcpyToSymbolAsync(c_sdw_b,  d_in[dw_w[sbx] + 1], 32*4,    g*32*4,    cudaMemcpyDeviceToDevice);
        cudaMemcpyToSymbolAsync(g_spw_w,  d_in[pw_w[sbx]],     32*32*4, g*32*32*4, cudaMemcpyDeviceToDevice);
        cudaMemcpyToSymbolAsync(g_spw_b,  d_in[pw_w[sbx] + 1], 32*4,    g*32*4,    cudaMemcpyDeviceToDevice);
    }
    cudaMemcpyToSymbolAsync(g_c5w,  d_in[idx_c5w],  Cn*9*4, 0, cudaMemcpyDeviceToDevice);
    cudaMemcpyToSymbolAsync(g_c5b,  d_in[idx_c5b],  Cn*4,   0, cudaMemcpyDeviceToDevice);
    cudaMemcpyToSymbolAsync(g_n2w,  d_in[idx_n2w],  Cn*4,   0, cudaMemcpyDeviceToDevice);
    cudaMemcpyToSymbolAsync(g_n2b,  d_in[idx_n2b],  Cn*4,   0, cudaMemcpyDeviceToDevice);
    cudaMemcpyToSymbolAsync(c_ldww, d_in[idx_ldww], Cn*9*4, 0, cudaMemcpyDeviceToDevice);
    cudaMemcpyToSymbolAsync(c_ldwb, d_in[idx_ldwb], Cn*4,   0, cudaMemcpyDeviceToDevice);
    cudaMemcpyToSymbolAsync(c_lpwb, d_in[idx_lpwb], Cn*4,   0, cudaMemcpyDeviceToDevice);

    const int smem2 = SMEM2_FLOATS * 4;
    cudaFuncSetAttribute(k2_mix,   cudaFuncAttributeMaxDynamicSharedMemorySize, smem2);
    cudaFuncSetAttribute(k3_final, cudaFuncAttributeMaxDynamicSharedMemorySize, SM3_TOTAL);

    k0_prep<<<64, 256>>>((const float*)d_in[idx_lpw]);
    k1_stats<<<NPIX/256, 256>>>(x);
    k2_mix<<<dim3(Wn/T2, Hn/T2, Bn), NT2, smem2>>>(x);
    k3_final<<<dim3(Wn/T3W, Hn/T3H, Bn), NT3, SM3_TOTAL>>>((float*)d_out);
}

// round 12
// speedup vs baseline: 2.6790x; 1.4254x over previous
#include <cuda_runtime.h>
#include <cuda_bf16.h>
#include <stdint.h>
#include <math.h>

#define Bn 8
#define Cn 128
#define Hn 224
#define Wn 224
#define HWn (Hn*Wn)        // 50176
#define CHWn (Cn*HWn)      // 6422528
#define NPIX (Bn*HWn)      // 401408

// ---------------- scratch (static device globals; no allocation) ----------------
__device__ float g_y[(long long)Bn*CHWn];   // LN2-normalized, shuffled tensor (205.5 MB)
__device__ float g_m1[NPIX];
__device__ float g_r1[NPIX];
__device__ float g_spw_w[4*32*32];   // [g][o][c], group order (s2,s4,s1,s3)
__device__ float g_spw_wT[4*32*32];  // [g][c][o]  (filled by k0_prep)
__device__ float g_spw_b[128];
__device__ float g_c5w[128*9];
__device__ float g_c5b[128];
__device__ float g_n2w[128];
__device__ float g_n2b[128];
// final pw weights, bf16 hi/lo split, plain [o][ch] layout (filled by k0_prep)
__device__ __align__(16) unsigned short g_pwbh[Cn*Cn];
__device__ __align__(16) unsigned short g_pwbl[Cn*Cn];

// ---------------- constant weights (warp-uniform access only) ----------------
__constant__ float c_n1w[Cn], c_n1b[Cn];
__constant__ float c_sdw_w[4][32][9];
__constant__ float c_sdw_b[4][32];
__constant__ float c_ldww[Cn][9];
__constant__ float c_ldwb[Cn];
__constant__ float c_lpwb[Cn];

__device__ __forceinline__ float gelu_exact(float x) {
    return 0.5f * x * (1.0f + erff(x * 0.70710678118654752f));
}

// split fp32 -> bf16 hi + bf16 lo
__device__ __forceinline__ void bf16_split(float v, unsigned short& hb, unsigned short& lb) {
    __nv_bfloat16 h = __float2bfloat16(v);
    float hf = __bfloat162float(h);
    __nv_bfloat16 l = __float2bfloat16(v - hf);
    hb = *(unsigned short*)&h;
    lb = *(unsigned short*)&l;
}

// warp-level bf16 MMA (sm_80+ path, valid on base sm_100)
__device__ __forceinline__ void mma16816(float* c, const uint32_t* a, const uint32_t* b) {
    asm volatile(
        "mma.sync.aligned.m16n8k16.row.col.f32.bf16.bf16.f32 "
        "{%0,%1,%2,%3}, {%4,%5,%6,%7}, {%8,%9}, {%0,%1,%2,%3};"
        : "+f"(c[0]), "+f"(c[1]), "+f"(c[2]), "+f"(c[3])
        : "r"(a[0]), "r"(a[1]), "r"(a[2]), "r"(a[3]), "r"(b[0]), "r"(b[1]));
}

// ================= kernel 0: prep weights =================
__global__ __launch_bounds__(256) void k0_prep(const float* __restrict__ pw)
{
    int i = blockIdx.x * 256 + threadIdx.x;
    if (i < Cn*Cn) {
        unsigned short hb, lb;
        bf16_split(pw[i], hb, lb);
        g_pwbh[i] = hb;      // [o][ch] row-major
        g_pwbl[i] = lb;
    }
    if (i < 4096) {
        int g = i >> 10, r = i & 1023, o = r >> 5, c = r & 31;
        g_spw_wT[g*1024 + c*32 + o] = g_spw_w[i];
    }
}

// ================= kernel 1: LN1 stats =================
__global__ __launch_bounds__(256) void k1_stats(const float* __restrict__ x)
{
    int idx = blockIdx.x * 256 + threadIdx.x;
    int b  = idx / HWn;
    int hw = idx - b * HWn;
    const float* px = x + b * CHWn + hw;
    float s = 0.f, ss = 0.f;
    #pragma unroll 8
    for (int ch = 0; ch < Cn; ch++) {
        float v = px[ch * HWn];
        s += v; ss = fmaf(v, v, ss);
    }
    float m = s * (1.0f/128.0f);
    float var = fmaf(-m, m, ss * (1.0f/128.0f));
    g_m1[idx] = m;
    g_r1[idx] = rsqrtf(var + 1e-6f);
}

// ================= kernel 2: branches + c5 + shuffle + LN2 (16x8 tile) =================
#define T2W 16
#define T2H 8
#define R2W 20
#define R2H 12
#define NPOS 240           // R2H*R2W
#define NT2 512
// smem layout (floats)
#define OFF_SX   0                       // [128][240]
#define OFF_ST   (OFF_SX + Cn*NPOS)      // 30720: t [128][128]
#define OFF_W2   (OFF_ST + Cn*128)       // 47104: spw_wT [4][32c][32o]
#define OFF_RED  (OFF_W2 + 4096)         // 51200: [2][4][128]
#define OFF_MS   (OFF_RED + 1024)        // 52224
#define OFF_RS   (OFF_MS + 128)
#define OFF_GAM  (OFF_RS + 128)
#define OFF_BET  (OFF_GAM + 128)
#define OFF_C5W  (OFF_BET + 128)         // [128][9]
#define OFF_C5B  (OFF_C5W + 1152)
#define OFF_PWB  (OFF_C5B + 128)
#define OFF_SM1  (OFF_PWB + 128)         // [240]
#define OFF_SR1  (OFF_SM1 + NPOS)
#define SMEM2_FLOATS (OFF_SR1 + NPOS)    // 54624 floats = 218496 B

__global__ __launch_bounds__(NT2, 1) void k2_mix(const float* __restrict__ x)
{
    extern __shared__ float sm[];
    const int b  = blockIdx.z;
    const int h0 = blockIdx.y * T2H;
    const int w0 = blockIdx.x * T2W;
    const int tid = threadIdx.x;
    const int wid = tid >> 5, lane = tid & 31;
    const long long xb = (long long)b * CHWn;

    // ---- stage stats halo + small weight tables ----
    if (tid < NPOS) {
        int r = tid / R2W, cc = tid - r * R2W;
        int gh = h0 + r - 2, gw = w0 + cc - 2;
        float m = 0.f, rs = 0.f;
        if ((unsigned)gh < (unsigned)Hn && (unsigned)gw < (unsigned)Wn) {
            int p = b * HWn + gh * Wn + gw;
            m = g_m1[p]; rs = g_r1[p];
        }
        sm[OFF_SM1 + tid] = m; sm[OFF_SR1 + tid] = rs;
    }
    for (int i = tid; i < 4096; i += NT2) sm[OFF_W2 + i] = g_spw_wT[i];
    for (int i = tid; i < 1152; i += NT2) sm[OFF_C5W + i] = g_c5w[i];
    if (tid < 128) {
        sm[OFF_C5B + tid] = g_c5b[tid];
        sm[OFF_PWB + tid] = g_spw_b[tid];
        sm[OFF_GAM + tid] = g_n2w[tid];
        sm[OFF_BET + tid] = g_n2b[tid];
    }
    __syncthreads();

    // ---- stage LN1(x) tile: hoisted per-pos metadata, warp-per-channel ----
    {
        int   gofs[8];
        float mV[8], rV[8];
        #pragma unroll
        for (int j = 0; j < 8; j++) {
            int pos = lane + 32 * j;
            bool ok = pos < NPOS;
            int r = pos / R2W, cc = pos - r * R2W;
            int gh = h0 + r - 2, gw = w0 + cc - 2;
            bool inb = ok && (unsigned)gh < (unsigned)Hn && (unsigned)gw < (unsigned)Wn;
            gofs[j] = inb ? (gh * Wn + gw) : -1;
            mV[j] = ok ? sm[OFF_SM1 + pos] : 0.f;
            rV[j] = ok ? sm[OFF_SR1 + pos] : 0.f;
        }
        for (int k = 0; k < 8; k++) {
            const int ch = wid + 16 * k;                  // warp-uniform
            const float gam = c_n1w[ch], bet = c_n1b[ch];
            const float* xc = x + xb + (long long)ch * HWn;
            #pragma unroll
            for (int j = 0; j < 8; j++) {
                int pos = lane + 32 * j;
                if (pos < NPOS) {
                    float v = 0.f;
                    if (gofs[j] >= 0) v = (xc[gofs[j]] - mV[j]) * rV[j] * gam + bet;
                    sm[OFF_SX + ch * NPOS + pos] = v;
                }
            }
        }
    }
    __syncthreads();

    // ---- phase B: pixel-pair dw3+gelu, 16 ch-iters ----
    {
        const int pairslot = tid & 63;
        const int px0 = pairslot & 15, py0 = (pairslot >> 4) * 2;
        const int chb = tid >> 6;                          // 0..7, warp-uniform
        bool myp[4], mx[3];
        #pragma unroll
        for (int k = 0; k < 4; k++) myp[k] = (unsigned)(h0 + py0 + k - 1) < (unsigned)Hn;
        #pragma unroll
        for (int d = 0; d < 3; d++)  mx[d]  = (unsigned)(w0 + px0 + d - 1) < (unsigned)Wn;

        #pragma unroll 2
        for (int it = 0; it < 16; it++) {
            const int ch = chb + it * 8;                   // warp-uniform
            const int gg = ch >> 5, cc = ch & 31;
            const int srcb = ((0x2031 >> (4*gg)) & 15) << 5;   // {32,96,0,64}
            const int offy = (0x2002 >> (4*gg)) & 15;          // 1 - shh
            const int offx = (0x2020 >> (4*gg)) & 15;          // 1 - shw
            const float* bp = sm + OFF_SX + (srcb + cc) * NPOS + (py0 + offy) * R2W + (px0 + offx);
            float aA = c_sdw_b[gg][cc], aB = aA;
            #pragma unroll
            for (int k = 0; k < 4; k++) {
                #pragma unroll
                for (int d = 0; d < 3; d++) {
                    float t = bp[k * R2W + d];
                    bool okc = myp[k] && mx[d];
                    if (k < 3 && okc) aA = fmaf(c_sdw_w[gg][cc][k*3 + d], t, aA);
                    if (k > 0 && okc) aB = fmaf(c_sdw_w[gg][cc][(k-1)*3 + d], t, aB);
                }
            }
            sm[OFF_ST + ch * 128 + py0 * 16 + px0]       = gelu_exact(aA);
            sm[OFF_ST + ch * 128 + (py0 + 1) * 16 + px0] = gelu_exact(aB);
        }
    }
    __syncthreads();

    // ---- phase C: pw GEMM (block-diag 32x32) + c5 residual + LN2 ----
    const int g    = tid >> 7;             // warp-uniform group
    const int oj   = tid & 3;              // o sub-slot (8 o each)
    const int qslot = (tid >> 2) & 31;
    const int qpix = qslot * 4;
    const int qy = qpix >> 4, qx = qpix & 15;

    float acc[8][4];
    #pragma unroll
    for (int j = 0; j < 8; j++) {
        float bj = sm[OFF_PWB + g * 32 + oj * 8 + j];
        acc[j][0] = bj; acc[j][1] = bj; acc[j][2] = bj; acc[j][3] = bj;
    }
    {
        const float* w2g = sm + OFF_W2 + g * 1024 + oj * 8;
        const float* stg = sm + OFF_ST + (g * 32) * 128 + qpix;
        #pragma unroll 8
        for (int c = 0; c < 32; c++) {
            float4 wa = *(const float4*)(w2g + c * 32);
            float4 wb = *(const float4*)(w2g + c * 32 + 4);
            float4 tv = *(const float4*)(stg + c * 128);
            acc[0][0]=fmaf(wa.x,tv.x,acc[0][0]); acc[0][1]=fmaf(wa.x,tv.y,acc[0][1]); acc[0][2]=fmaf(wa.x,tv.z,acc[0][2]); acc[0][3]=fmaf(wa.x,tv.w,acc[0][3]);
            acc[1][0]=fmaf(wa.y,tv.x,acc[1][0]); acc[1][1]=fmaf(wa.y,tv.y,acc[1][1]); acc[1][2]=fmaf(wa.y,tv.z,acc[1][2]); acc[1][3]=fmaf(wa.y,tv.w,acc[1][3]);
            acc[2][0]=fmaf(wa.z,tv.x,acc[2][0]); acc[2][1]=fmaf(wa.z,tv.y,acc[2][1]); acc[2][2]=fmaf(wa.z,tv.z,acc[2][2]); acc[2][3]=fmaf(wa.z,tv.w,acc[2][3]);
            acc[3][0]=fmaf(wa.w,tv.x,acc[3][0]); acc[3][1]=fmaf(wa.w,tv.y,acc[3][1]); acc[3][2]=fmaf(wa.w,tv.z,acc[3][2]); acc[3][3]=fmaf(wa.w,tv.w,acc[3][3]);
            acc[4][0]=fmaf(wb.x,tv.x,acc[4][0]); acc[4][1]=fmaf(wb.x,tv.y,acc[4][1]); acc[4][2]=fmaf(wb.x,tv.z,acc[4][2]); acc[4][3]=fmaf(wb.x,tv.w,acc[4][3]);
            acc[5][0]=fmaf(wb.y,tv.x,acc[5][0]); acc[5][1]=fmaf(wb.y,tv.y,acc[5][1]); acc[5][2]=fmaf(wb.y,tv.z,acc[5][2]); acc[5][3]=fmaf(wb.y,tv.w,acc[5][3]);
            acc[6][0]=fmaf(wb.z,tv.x,acc[6][0]); acc[6][1]=fmaf(wb.z,tv.y,acc[6][1]); acc[6][2]=fmaf(wb.z,tv.z,acc[6][2]); acc[6][3]=fmaf(wb.z,tv.w,acc[6][3]);
            acc[7][0]=fmaf(wb.w,tv.x,acc[7][0]); acc[7][1]=fmaf(wb.w,tv.y,acc[7][1]); acc[7][2]=fmaf(wb.w,tv.z,acc[7][2]); acc[7][3]=fmaf(wb.w,tv.w,acc[7][3]);
        }
    }
    // c5 residual (unshifted dw3 of LN1(x); zero halo = SAME pad)
    #pragma unroll
    for (int j = 0; j < 8; j++) {
        const int ci = g * 32 + oj * 8 + j;
        const float* cw = sm + OFF_C5W + ci * 9;
        const float* bp = sm + OFF_SX + ci * NPOS + (qy + 1) * R2W + (qx + 1);
        const float b5 = sm[OFF_C5B + ci];
        #pragma unroll
        for (int i = 0; i < 4; i++) {
            float a5 = b5;
            #pragma unroll
            for (int k = 0; k < 9; k++)
                a5 = fmaf(cw[k], bp[(k/3)*R2W + (k%3) + i], a5);
            acc[j][i] += a5;
        }
    }
    // ---- LN2 stats: shfl over oj (bits 0-1), then tiny cross-g smem pass ----
    {
        float ps[4] = {0,0,0,0}, pq[4] = {0,0,0,0};
        #pragma unroll
        for (int j = 0; j < 8; j++)
            #pragma unroll
            for (int i = 0; i < 4; i++) { ps[i] += acc[j][i]; pq[i] = fmaf(acc[j][i], acc[j][i], pq[i]); }
        #pragma unroll
        for (int d = 1; d <= 2; d <<= 1) {
            #pragma unroll
            for (int i = 0; i < 4; i++) {
                ps[i] += __shfl_xor_sync(0xFFFFFFFFu, ps[i], d);
                pq[i] += __shfl_xor_sync(0xFFFFFFFFu, pq[i], d);
            }
        }
        if (oj == 0) {
            *(float4*)&sm[OFF_RED + g * 128 + qpix]       = make_float4(ps[0], ps[1], ps[2], ps[3]);
            *(float4*)&sm[OFF_RED + 512 + g * 128 + qpix] = make_float4(pq[0], pq[1], pq[2], pq[3]);
        }
    }
    __syncthreads();
    if (tid < 128) {
        float s = 0.f, ss = 0.f;
        #pragma unroll
        for (int g2 = 0; g2 < 4; g2++) {
            s  += sm[OFF_RED + g2 * 128 + tid];
            ss += sm[OFF_RED + 512 + g2 * 128 + tid];
        }
        float m = s * (1.0f/128.0f);
        float var = fmaf(-m, m, ss * (1.0f/128.0f));
        sm[OFF_MS + tid] = m;
        sm[OFF_RS + tid] = rsqrtf(var + 1e-6f);
    }
    __syncthreads();

    // ---- normalize (LN2) + shuffle + store ----
    float mv[4], rv[4];
    #pragma unroll
    for (int i = 0; i < 4; i++) { mv[i] = sm[OFF_MS + qpix + i]; rv[i] = sm[OFF_RS + qpix + i]; }
    const long long obase = xb + (long long)(h0 + qy) * Wn + (w0 + qx);
    #pragma unroll
    for (int j = 0; j < 8; j++) {
        const int ci = g * 32 + oj * 8 + j;
        const int ko = ((ci & 63) << 1) | (ci >> 6);   // channel shuffle, 2 groups
        const float gam = sm[OFF_GAM + ko], bet = sm[OFF_BET + ko];
        float4 ov;
        ov.x = fmaf((acc[j][0] - mv[0]) * rv[0], gam, bet);
        ov.y = fmaf((acc[j][1] - mv[1]) * rv[1], gam, bet);
        ov.z = fmaf((acc[j][2] - mv[2]) * rv[2], gam, bet);
        ov.w = fmaf((acc[j][3] - mv[3]) * rv[3], gam, bet);
        *(float4*)&g_y[obase + (long long)ko * HWn] = ov;
    }
}

// ================= kernel 3: dw3(gelu) + mma.sync bf16-split GEMM (unchanged) =================
#define T3W 16
#define T3H 8
#define R3H 10
#define R3W 18
#define NT3 512
#define AS3 136                        // bf16 row stride (272B): conflict-free frags
#define SM3_AH   0
#define SM3_AL   (SM3_AH + 128*AS3*2)   // 34816
#define SM3_BH   (SM3_AL + 128*AS3*2)   // 69632
#define SM3_BL   (SM3_BH + 128*AS3*2)   // 104448
#define SM3_Y    (SM3_BL + 128*AS3*2)   // 139264
#define SM3_BIAS (SM3_Y + 64*R3H*R3W*4) // 185344
#define SM3_TOTAL (SM3_BIAS + 512)      // 185856 bytes

__global__ __launch_bounds__(NT3, 1) void k3_final(float* __restrict__ out)
{
    extern __shared__ char smc[];
    float* ysm  = (float*)(smc + SM3_Y);
    float* bias = (float*)(smc + SM3_BIAS);
    const int b  = blockIdx.z;
    const int h0 = blockIdx.y * T3H;
    const int w0 = blockIdx.x * T3W;
    const int tid = threadIdx.x;
    const int wid = tid >> 5, lane = tid & 31;
    const long long xb = (long long)b * CHWn;

    for (int i = tid; i < 4096; i += NT3) {
        int o = i >> 5, qq = i & 31;
        *(uint2*)(smc + SM3_BH + o * (AS3*2) + qq * 8) = ((const uint2*)g_pwbh)[i];
        *(uint2*)(smc + SM3_BL + o * (AS3*2) + qq * 8) = ((const uint2*)g_pwbl)[i];
    }
    if (tid < 128) bias[tid] = c_lpwb[tid];

    for (int h2 = 0; h2 < 2; h2++) {
        __syncthreads();
        for (int i = tid; i < 64 * R3H * R3W; i += NT3) {
            int ch = i / (R3H * R3W);
            int pos = i - ch * (R3H * R3W);
            int r = pos / R3W, cc = pos - r * R3W;
            int gh = h0 + r - 1, gw = w0 + cc - 1;
            float v = 0.f;
            if ((unsigned)gh < (unsigned)Hn && (unsigned)gw < (unsigned)Wn)
                v = g_y[xb + (long long)(h2 * 64 + ch) * HWn + gh * Wn + gw];
            ysm[i] = v;
        }
        __syncthreads();
        for (int i = tid; i < 64 * 128; i += NT3) {
            int chl = i >> 7, p = i & 127;
            int ch = h2 * 64 + chl;
            int py = p >> 4, pxx = p & 15;
            const float* bp = ysm + chl * (R3H * R3W) + py * R3W + pxx;
            float a = c_ldwb[ch];
            #pragma unroll
            for (int k = 0; k < 9; k++)
                a = fmaf(c_ldww[ch][k], bp[(k/3)*R3W + (k%3)], a);
            float v = gelu_exact(a);
            unsigned short hb, lb;
            bf16_split(v, hb, lb);
            *(unsigned short*)(smc + SM3_AH + p * (AS3*2) + ch * 2) = hb;
            *(unsigned short*)(smc + SM3_AL + p * (AS3*2) + ch * 2) = lb;
        }
    }
    __syncthreads();

    const int mi = wid >> 2, ni = wid & 3;
    const int lr = lane >> 2, lc = lane & 3;
    float cfr[8][4];
    #pragma unroll
    for (int t = 0; t < 8; t++) { cfr[t][0]=0.f; cfr[t][1]=0.f; cfr[t][2]=0.f; cfr[t][3]=0.f; }

    #pragma unroll
    for (int pass = 0; pass < 3; pass++) {
        const char* Ab = smc + (pass == 2 ? SM3_AL : SM3_AH);
        const char* Bb = smc + (pass == 1 ? SM3_BL : SM3_BH);
        #pragma unroll
        for (int k0 = 0; k0 < 8; k0++) {
            const int kb = k0 * 16;
            uint32_t a[2][4], bfr[4][2];
            #pragma unroll
            for (int m2 = 0; m2 < 2; m2++) {
                const char* ap = Ab + (mi*32 + m2*16 + lr) * (AS3*2) + (kb + lc*2) * 2;
                a[m2][0] = *(const uint32_t*)(ap);
                a[m2][1] = *(const uint32_t*)(ap + 8 * (AS3*2));
                a[m2][2] = *(const uint32_t*)(ap + 16);
                a[m2][3] = *(const uint32_t*)(ap + 8 * (AS3*2) + 16);
            }
            #pragma unroll
            for (int n4 = 0; n4 < 4; n4++) {
                const char* bp = Bb + (ni*32 + n4*8 + lr) * (AS3*2) + (kb + lc*2) * 2;
                bfr[n4][0] = *(const uint32_t*)(bp);
                bfr[n4][1] = *(const uint32_t*)(bp + 16);
            }
            #pragma unroll
            for (int m2 = 0; m2 < 2; m2++)
                #pragma unroll
                for (int n4 = 0; n4 < 4; n4++)
                    mma16816(cfr[m2*4 + n4], a[m2], bfr[n4]);
        }
    }

    #pragma unroll
    for (int m2 = 0; m2 < 2; m2++) {
        #pragma unroll
        for (int n4 = 0; n4 < 4; n4++) {
            const float* cf = cfr[m2*4 + n4];
            const int p0 = mi*32 + m2*16 + lr;
            const int p1 = p0 + 8;
            const int oo = ni*32 + n4*8 + lc*2;
            const float b0v = bias[oo], b1v = bias[oo + 1];
            const long long r0 = xb + (long long)(h0 + (p0 >> 4)) * Wn + (w0 + (p0 & 15));
            const long long r1 = xb + (long long)(h0 + (p1 >> 4)) * Wn + (w0 + (p1 & 15));
            out[r0 + (long long)oo * HWn]       = cf[0] + b0v;
            out[r0 + (long long)(oo+1) * HWn]   = cf[1] + b1v;
            out[r1 + (long long)oo * HWn]       = cf[2] + b0v;
            out[r1 + (long long)(oo+1) * HWn]   = cf[3] + b1v;
        }
    }
}

// ================= launch =================
extern "C" void kernel_launch(void* const* d_in, const int* in_sizes, int n_in,
                              void* d_out, int out_size)
{
    (void)out_size;
    int idx_x = 0, idx_lpw = -1, idx_c5w = -1, idx_ldww = -1;
    int dw_w[4] = {-1,-1,-1,-1}, pw_w[4] = {-1,-1,-1,-1};
    int ndw = 0, npw = 0;
    for (int i = 0; i < n_in; i++) {
        int s = in_sizes[i];
        if (s > 100000)      idx_x = i;
        else if (s == 16384) idx_lpw = i;
        else if (s == 1152)  { if (idx_c5w < 0) idx_c5w = i; else idx_ldww = i; }
        else if (s == 288 && ndw < 4)  dw_w[ndw++] = i;
        else if (s == 1024 && npw < 4) pw_w[npw++] = i;
    }
    const int idx_c5b  = idx_c5w  + 1;
    const int idx_ldwb = idx_ldww + 1;
    const int idx_lpwb = idx_lpw  + 1;
    int v128[8]; int nv = 0;
    for (int i = 0; i < n_in; i++)
        if (in_sizes[i] == 128 && i != idx_c5b && i != idx_ldwb && i != idx_lpwb && nv < 8)
            v128[nv++] = i;
    const int idx_n1w = v128[0], idx_n1b = v128[1];
    const int idx_n2w = v128[2], idx_n2b = v128[3];

    const float* x = (const float*)d_in[idx_x];

    cudaMemcpyToSymbolAsync(c_n1w, d_in[idx_n1w], Cn*4, 0, cudaMemcpyDeviceToDevice);
    cudaMemcpyToSymbolAsync(c_n1b, d_in[idx_n1b], Cn*4, 0, cudaMemcpyDeviceToDevice);
    const int GS[4] = {1, 3, 0, 2};
    for (int g = 0; g < 4; g++) {
        int sbx = GS[g];
        cudaMemcpyToSymbolAsync(c_sdw_w,  d_in[dw_w[sbx]],     32*9*4,  g*32*9*4,  cudaMemcpyDeviceToDevice);
        cudaMemcpyToSymbolAsync(c_sdw_b,  d_in[dw_w[sbx] + 1], 32*4,    g*32*4,    cudaMemcpyDeviceToDevice);
        cudaMemcpyToSymbolAsync(g_spw_w,  d_in[pw_w[sbx]],     32*32*4, g*32*32*4, cudaMemcpyDeviceToDevice);
        cudaMemcpyToSymbolAsync(g_spw_b,  d_in[pw_w[sbx] + 1], 32*4,    g*32*4,    cudaMemcpyDeviceToDevice);
    }
    cudaMemcpyToSymbolAsync(g_c5w,  d_in[idx_c5w],  Cn*9*4, 0, cudaMemcpyDeviceToDevice);
    cudaMemcpyToSymbolAsync(g_c5b,  d_in[idx_c5b],  Cn*4,   0, cudaMemcpyDeviceToDevice);
    cudaMemcpyToSymbolAsync(g_n2w,  d_in[idx_n2w],  Cn*4,   0, cudaMemcpyDeviceToDevice);
    cudaMemcpyToSymbolAsync(g_n2b,  d_in[idx_n2b],  Cn*4,   0, cudaMemcpyDeviceToDevice);
    cudaMemcpyToSymbolAsync(c_ldww, d_in[idx_ldww], Cn*9*4, 0, cudaMemcpyDeviceToDevice);
    cudaMemcpyToSymbolAsync(c_ldwb, d_in[idx_ldwb], Cn*4,   0, cudaMemcpyDeviceToDevice);
    cudaMemcpyToSymbolAsync(c_lpwb, d_in[idx_lpwb], Cn*4,   0, cudaMemcpyDeviceToDevice);

    const int smem2 = SMEM2_FLOATS * 4;
    cudaFuncSetAttribute(k2_mix,   cudaFuncAttributeMaxDynamicSharedMemorySize, smem2);
    cudaFuncSetAttribute(k3_final, cudaFuncAttributeMaxDynamicSharedMemorySize, SM3_TOTAL);

    k0_prep<<<64, 256>>>((const float*)d_in[idx_lpw]);
    k1_stats<<<NPIX/256, 256>>>(x);
    k2_mix<<<dim3(Wn/T2W, Hn/T2H, Bn), NT2, smem2>>>(x);
    k3_final<<<dim3(Wn/T3W, Hn/T3H, Bn), NT3, SM3_TOTAL>>>((float*)d_out);
}

// round 13
// speedup vs baseline: 2.8502x; 1.0639x over previous
#include <cuda_runtime.h>
#include <cuda_bf16.h>
#include <stdint.h>
#include <math.h>

#define Bn 8
#define Cn 128
#define Hn 224
#define Wn 224
#define HWn (Hn*Wn)        // 50176
#define CHWn (Cn*HWn)      // 6422528
#define NPIX (Bn*HWn)      // 401408

// ---------------- scratch (static device globals; no allocation) ----------------
__device__ float g_y[(long long)Bn*CHWn];   // LN2-normalized, shuffled tensor (205.5 MB)
__device__ float g_m1[NPIX];
__device__ float g_r1[NPIX];
__device__ float g_spw_w[4*32*32];   // [g][o][c], group order (s2,s4,s1,s3)
__device__ float g_spw_wT[4*32*32];  // [g][c][o]  (filled by k0_prep)
__device__ float g_spw_b[128];
__device__ float g_c5w[128*9];
__device__ float g_c5b[128];
__device__ float g_n2w[128];
__device__ float g_n2b[128];
// final pw weights, bf16 hi/lo split, plain [o][ch] layout (filled by k0_prep)
__device__ __align__(16) unsigned short g_pwbh[Cn*Cn];
__device__ __align__(16) unsigned short g_pwbl[Cn*Cn];

// ---------------- constant weights (warp-uniform access only) ----------------
__constant__ float c_n1w[Cn], c_n1b[Cn];
__constant__ float c_sdw_w[4][32][9];
__constant__ float c_sdw_b[4][32];
__constant__ float c_ldww[Cn][9];
__constant__ float c_ldwb[Cn];
__constant__ float c_lpwb[Cn];

__device__ __forceinline__ float gelu_exact(float x) {
    return 0.5f * x * (1.0f + erff(x * 0.70710678118654752f));
}

// split fp32 -> bf16 hi + bf16 lo
__device__ __forceinline__ void bf16_split(float v, unsigned short& hb, unsigned short& lb) {
    __nv_bfloat16 h = __float2bfloat16(v);
    float hf = __bfloat162float(h);
    __nv_bfloat16 l = __float2bfloat16(v - hf);
    hb = *(unsigned short*)&h;
    lb = *(unsigned short*)&l;
}

// warp-level bf16 MMA (sm_80+ path, valid on base sm_100)
__device__ __forceinline__ void mma16816(float* c, const uint32_t* a, const uint32_t* b) {
    asm volatile(
        "mma.sync.aligned.m16n8k16.row.col.f32.bf16.bf16.f32 "
        "{%0,%1,%2,%3}, {%4,%5,%6,%7}, {%8,%9}, {%0,%1,%2,%3};"
        : "+f"(c[0]), "+f"(c[1]), "+f"(c[2]), "+f"(c[3])
        : "r"(a[0]), "r"(a[1]), "r"(a[2]), "r"(a[3]), "r"(b[0]), "r"(b[1]));
}

// ================= kernel 0: prep weights =================
__global__ __launch_bounds__(256) void k0_prep(const float* __restrict__ pw)
{
    int i = blockIdx.x * 256 + threadIdx.x;
    if (i < Cn*Cn) {
        unsigned short hb, lb;
        bf16_split(pw[i], hb, lb);
        g_pwbh[i] = hb;      // [o][ch] row-major
        g_pwbl[i] = lb;
    }
    if (i < 4096) {
        int g = i >> 10, r = i & 1023, o = r >> 5, c = r & 31;
        g_spw_wT[g*1024 + c*32 + o] = g_spw_w[i];
    }
}

// ================= kernel 1: LN1 stats =================
__global__ __launch_bounds__(256) void k1_stats(const float* __restrict__ x)
{
    int idx = blockIdx.x * 256 + threadIdx.x;
    int b  = idx / HWn;
    int hw = idx - b * HWn;
    const float* px = x + b * CHWn + hw;
    float s = 0.f, ss = 0.f;
    #pragma unroll 8
    for (int ch = 0; ch < Cn; ch++) {
        float v = px[ch * HWn];
        s += v; ss = fmaf(v, v, ss);
    }
    float m = s * (1.0f/128.0f);
    float var = fmaf(-m, m, ss * (1.0f/128.0f));
    g_m1[idx] = m;
    g_r1[idx] = rsqrtf(var + 1e-6f);
}

// ================= kernel 2: branches + c5 + shuffle + LN2 (unchanged from R12) =================
#define T2W 16
#define T2H 8
#define R2W 20
#define R2H 12
#define NPOS 240           // R2H*R2W
#define NT2 512
#define OFF_SX   0                       // [128][240]
#define OFF_ST   (OFF_SX + Cn*NPOS)      // 30720: t [128][128]
#define OFF_W2   (OFF_ST + Cn*128)       // 47104: spw_wT [4][32c][32o]
#define OFF_RED  (OFF_W2 + 4096)         // 51200: [2][4][128]
#define OFF_MS   (OFF_RED + 1024)        // 52224
#define OFF_RS   (OFF_MS + 128)
#define OFF_GAM  (OFF_RS + 128)
#define OFF_BET  (OFF_GAM + 128)
#define OFF_C5W  (OFF_BET + 128)         // [128][9]
#define OFF_C5B  (OFF_C5W + 1152)
#define OFF_PWB  (OFF_C5B + 128)
#define OFF_SM1  (OFF_PWB + 128)         // [240]
#define OFF_SR1  (OFF_SM1 + NPOS)
#define SMEM2_FLOATS (OFF_SR1 + NPOS)    // 54624 floats = 218496 B

__global__ __launch_bounds__(NT2, 1) void k2_mix(const float* __restrict__ x)
{
    extern __shared__ float sm[];
    const int b  = blockIdx.z;
    const int h0 = blockIdx.y * T2H;
    const int w0 = blockIdx.x * T2W;
    const int tid = threadIdx.x;
    const int wid = tid >> 5, lane = tid & 31;
    const long long xb = (long long)b * CHWn;

    if (tid < NPOS) {
        int r = tid / R2W, cc = tid - r * R2W;
        int gh = h0 + r - 2, gw = w0 + cc - 2;
        float m = 0.f, rs = 0.f;
        if ((unsigned)gh < (unsigned)Hn && (unsigned)gw < (unsigned)Wn) {
            int p = b * HWn + gh * Wn + gw;
            m = g_m1[p]; rs = g_r1[p];
        }
        sm[OFF_SM1 + tid] = m; sm[OFF_SR1 + tid] = rs;
    }
    for (int i = tid; i < 4096; i += NT2) sm[OFF_W2 + i] = g_spw_wT[i];
    for (int i = tid; i < 1152; i += NT2) sm[OFF_C5W + i] = g_c5w[i];
    if (tid < 128) {
        sm[OFF_C5B + tid] = g_c5b[tid];
        sm[OFF_PWB + tid] = g_spw_b[tid];
        sm[OFF_GAM + tid] = g_n2w[tid];
        sm[OFF_BET + tid] = g_n2b[tid];
    }
    __syncthreads();

    {
        int   gofs[8];
        float mV[8], rV[8];
        #pragma unroll
        for (int j = 0; j < 8; j++) {
            int pos = lane + 32 * j;
            bool ok = pos < NPOS;
            int r = pos / R2W, cc = pos - r * R2W;
            int gh = h0 + r - 2, gw = w0 + cc - 2;
            bool inb = ok && (unsigned)gh < (unsigned)Hn && (unsigned)gw < (unsigned)Wn;
            gofs[j] = inb ? (gh * Wn + gw) : -1;
            mV[j] = ok ? sm[OFF_SM1 + pos] : 0.f;
            rV[j] = ok ? sm[OFF_SR1 + pos] : 0.f;
        }
        for (int k = 0; k < 8; k++) {
            const int ch = wid + 16 * k;
            const float gam = c_n1w[ch], bet = c_n1b[ch];
            const float* xc = x + xb + (long long)ch * HWn;
            #pragma unroll
            for (int j = 0; j < 8; j++) {
                int pos = lane + 32 * j;
                if (pos < NPOS) {
                    float v = 0.f;
                    if (gofs[j] >= 0) v = (xc[gofs[j]] - mV[j]) * rV[j] * gam + bet;
                    sm[OFF_SX + ch * NPOS + pos] = v;
                }
            }
        }
    }
    __syncthreads();

    {
        const int pairslot = tid & 63;
        const int px0 = pairslot & 15, py0 = (pairslot >> 4) * 2;
        const int chb = tid >> 6;
        bool myp[4], mx[3];
        #pragma unroll
        for (int k = 0; k < 4; k++) myp[k] = (unsigned)(h0 + py0 + k - 1) < (unsigned)Hn;
        #pragma unroll
        for (int d = 0; d < 3; d++)  mx[d]  = (unsigned)(w0 + px0 + d - 1) < (unsigned)Wn;

        #pragma unroll 2
        for (int it = 0; it < 16; it++) {
            const int ch = chb + it * 8;
            const int gg = ch >> 5, cc = ch & 31;
            const int srcb = ((0x2031 >> (4*gg)) & 15) << 5;
            const int offy = (0x2002 >> (4*gg)) & 15;
            const int offx = (0x2020 >> (4*gg)) & 15;
            const float* bp = sm + OFF_SX + (srcb + cc) * NPOS + (py0 + offy) * R2W + (px0 + offx);
            float aA = c_sdw_b[gg][cc], aB = aA;
            #pragma unroll
            for (int k = 0; k < 4; k++) {
                #pragma unroll
                for (int d = 0; d < 3; d++) {
                    float t = bp[k * R2W + d];
                    bool okc = myp[k] && mx[d];
                    if (k < 3 && okc) aA = fmaf(c_sdw_w[gg][cc][k*3 + d], t, aA);
                    if (k > 0 && okc) aB = fmaf(c_sdw_w[gg][cc][(k-1)*3 + d], t, aB);
                }
            }
            sm[OFF_ST + ch * 128 + py0 * 16 + px0]       = gelu_exact(aA);
            sm[OFF_ST + ch * 128 + (py0 + 1) * 16 + px0] = gelu_exact(aB);
        }
    }
    __syncthreads();

    const int g    = tid >> 7;
    const int oj   = tid & 3;
    const int qslot = (tid >> 2) & 31;
    const int qpix = qslot * 4;
    const int qy = qpix >> 4, qx = qpix & 15;

    float acc[8][4];
    #pragma unroll
    for (int j = 0; j < 8; j++) {
        float bj = sm[OFF_PWB + g * 32 + oj * 8 + j];
        acc[j][0] = bj; acc[j][1] = bj; acc[j][2] = bj; acc[j][3] = bj;
    }
    {
        const float* w2g = sm + OFF_W2 + g * 1024 + oj * 8;
        const float* stg = sm + OFF_ST + (g * 32) * 128 + qpix;
        #pragma unroll 8
        for (int c = 0; c < 32; c++) {
            float4 wa = *(const float4*)(w2g + c * 32);
            float4 wb = *(const float4*)(w2g + c * 32 + 4);
            float4 tv = *(const float4*)(stg + c * 128);
            acc[0][0]=fmaf(wa.x,tv.x,acc[0][0]); acc[0][1]=fmaf(wa.x,tv.y,acc[0][1]); acc[0][2]=fmaf(wa.x,tv.z,acc[0][2]); acc[0][3]=fmaf(wa.x,tv.w,acc[0][3]);
            acc[1][0]=fmaf(wa.y,tv.x,acc[1][0]); acc[1][1]=fmaf(wa.y,tv.y,acc[1][1]); acc[1][2]=fmaf(wa.y,tv.z,acc[1][2]); acc[1][3]=fmaf(wa.y,tv.w,acc[1][3]);
            acc[2][0]=fmaf(wa.z,tv.x,acc[2][0]); acc[2][1]=fmaf(wa.z,tv.y,acc[2][1]); acc[2][2]=fmaf(wa.z,tv.z,acc[2][2]); acc[2][3]=fmaf(wa.z,tv.w,acc[2][3]);
            acc[3][0]=fmaf(wa.w,tv.x,acc[3][0]); acc[3][1]=fmaf(wa.w,tv.y,acc[3][1]); acc[3][2]=fmaf(wa.w,tv.z,acc[3][2]); acc[3][3]=fmaf(wa.w,tv.w,acc[3][3]);
            acc[4][0]=fmaf(wb.x,tv.x,acc[4][0]); acc[4][1]=fmaf(wb.x,tv.y,acc[4][1]); acc[4][2]=fmaf(wb.x,tv.z,acc[4][2]); acc[4][3]=fmaf(wb.x,tv.w,acc[4][3]);
            acc[5][0]=fmaf(wb.y,tv.x,acc[5][0]); acc[5][1]=fmaf(wb.y,tv.y,acc[5][1]); acc[5][2]=fmaf(wb.y,tv.z,acc[5][2]); acc[5][3]=fmaf(wb.y,tv.w,acc[5][3]);
            acc[6][0]=fmaf(wb.z,tv.x,acc[6][0]); acc[6][1]=fmaf(wb.z,tv.y,acc[6][1]); acc[6][2]=fmaf(wb.z,tv.z,acc[6][2]); acc[6][3]=fmaf(wb.z,tv.w,acc[6][3]);
            acc[7][0]=fmaf(wb.w,tv.x,acc[7][0]); acc[7][1]=fmaf(wb.w,tv.y,acc[7][1]); acc[7][2]=fmaf(wb.w,tv.z,acc[7][2]); acc[7][3]=fmaf(wb.w,tv.w,acc[7][3]);
        }
    }
    #pragma unroll
    for (int j = 0; j < 8; j++) {
        const int ci = g * 32 + oj * 8 + j;
        const float* cw = sm + OFF_C5W + ci * 9;
        const float* bp = sm + OFF_SX + ci * NPOS + (qy + 1) * R2W + (qx + 1);
        const float b5 = sm[OFF_C5B + ci];
        #pragma unroll
        for (int i = 0; i < 4; i++) {
            float a5 = b5;
            #pragma unroll
            for (int k = 0; k < 9; k++)
                a5 = fmaf(cw[k], bp[(k/3)*R2W + (k%3) + i], a5);
            acc[j][i] += a5;
        }
    }
    {
        float ps[4] = {0,0,0,0}, pq[4] = {0,0,0,0};
        #pragma unroll
        for (int j = 0; j < 8; j++)
            #pragma unroll
            for (int i = 0; i < 4; i++) { ps[i] += acc[j][i]; pq[i] = fmaf(acc[j][i], acc[j][i], pq[i]); }
        #pragma unroll
        for (int d = 1; d <= 2; d <<= 1) {
            #pragma unroll
            for (int i = 0; i < 4; i++) {
                ps[i] += __shfl_xor_sync(0xFFFFFFFFu, ps[i], d);
                pq[i] += __shfl_xor_sync(0xFFFFFFFFu, pq[i], d);
            }
        }
        if (oj == 0) {
            *(float4*)&sm[OFF_RED + g * 128 + qpix]       = make_float4(ps[0], ps[1], ps[2], ps[3]);
            *(float4*)&sm[OFF_RED + 512 + g * 128 + qpix] = make_float4(pq[0], pq[1], pq[2], pq[3]);
        }
    }
    __syncthreads();
    if (tid < 128) {
        float s = 0.f, ss = 0.f;
        #pragma unroll
        for (int g2 = 0; g2 < 4; g2++) {
            s  += sm[OFF_RED + g2 * 128 + tid];
            ss += sm[OFF_RED + 512 + g2 * 128 + tid];
        }
        float m = s * (1.0f/128.0f);
        float var = fmaf(-m, m, ss * (1.0f/128.0f));
        sm[OFF_MS + tid] = m;
        sm[OFF_RS + tid] = rsqrtf(var + 1e-6f);
    }
    __syncthreads();

    float mv[4], rv[4];
    #pragma unroll
    for (int i = 0; i < 4; i++) { mv[i] = sm[OFF_MS + qpix + i]; rv[i] = sm[OFF_RS + qpix + i]; }
    const long long obase = xb + (long long)(h0 + qy) * Wn + (w0 + qx);
    #pragma unroll
    for (int j = 0; j < 8; j++) {
        const int ci = g * 32 + oj * 8 + j;
        const int ko = ((ci & 63) << 1) | (ci >> 6);
        const float gam = sm[OFF_GAM + ko], bet = sm[OFF_BET + ko];
        float4 ov;
        ov.x = fmaf((acc[j][0] - mv[0]) * rv[0], gam, bet);
        ov.y = fmaf((acc[j][1] - mv[1]) * rv[1], gam, bet);
        ov.z = fmaf((acc[j][2] - mv[2]) * rv[2], gam, bet);
        ov.w = fmaf((acc[j][3] - mv[3]) * rv[3], gam, bet);
        *(float4*)&g_y[obase + (long long)ko * HWn] = ov;
    }
}

// ================= kernel 3: dw3(gelu) + mma.sync bf16-split GEMM =================
// tile 16w x 8h = 128 px; 512 threads; chunked double-buffered staging + packed A-writes.
#define T3W 16
#define T3H 8
#define R3H 10
#define R3W 18
#define NT3 512
#define YCH 32                         // channels per staging chunk
#define YPOS (R3H*R3W)                 // 180
#define AS3 136                        // bf16 row stride (272B): conflict-free frags
#define SM3_AH   0
#define SM3_AL   (SM3_AH + 128*AS3*2)   // 34816
#define SM3_BH   (SM3_AL + 128*AS3*2)   // 69632
#define SM3_BL   (SM3_BH + 128*AS3*2)   // 104448
#define SM3_Y    (SM3_BL + 128*AS3*2)   // 139264: 2 x [32][180] fp32
#define SM3_BIAS (SM3_Y + 2*YCH*YPOS*4) // 185344
#define SM3_TOTAL (SM3_BIAS + 512)      // 185856 bytes

__global__ __launch_bounds__(NT3, 1) void k3_final(float* __restrict__ out)
{
    extern __shared__ char smc[];
    float* bias = (float*)(smc + SM3_BIAS);
    const int b  = blockIdx.z;
    const int h0 = blockIdx.y * T3H;
    const int w0 = blockIdx.x * T3W;
    const int tid = threadIdx.x;
    const int wid = tid >> 5, lane = tid & 31;
    const long long xb = (long long)b * CHWn;
    float* ybuf0 = (float*)(smc + SM3_Y);
    float* ybuf1 = ybuf0 + YCH * YPOS;

    // stage B hi/lo (long-latency loads issue first)
    for (int i = tid; i < 4096; i += NT3) {
        int o = i >> 5, qq = i & 31;
        *(uint2*)(smc + SM3_BH + o * (AS3*2) + qq * 8) = ((const uint2*)g_pwbh)[i];
        *(uint2*)(smc + SM3_BL + o * (AS3*2) + qq * 8) = ((const uint2*)g_pwbl)[i];
    }
    if (tid < 128) bias[tid] = c_lpwb[tid];

    // hoisted per-lane staging metadata for pos = lane + 32*j (j<6)
    int goff[6];
    #pragma unroll
    for (int j = 0; j < 6; j++) {
        int pos = lane + 32 * j;
        bool ok = pos < YPOS;
        int r = pos / R3W, cc = pos - r * R3W;
        int gh = h0 + r - 1, gw = w0 + cc - 1;
        bool inb = ok && (unsigned)gh < (unsigned)Hn && (unsigned)gw < (unsigned)Wn;
        goff[j] = inb ? (gh * Wn + gw) : -1;
    }

    // staging helper (inlined twice): chunk q -> buf
    // compute helper: dw3+gelu+split for chunk q from buf, 4-ch packed writes
    // pipeline: stage(0); sync; { stage(q+1); compute(q); sync; }
    {
        // stage chunk 0 into ybuf0
        for (int c2 = wid; c2 < YCH; c2 += 16) {
            const float* yc = g_y + xb + (long long)c2 * HWn;
            float* dst = ybuf0 + c2 * YPOS;
            #pragma unroll
            for (int j = 0; j < 6; j++) {
                int pos = lane + 32 * j;
                if (pos < YPOS) dst[pos] = (goff[j] >= 0) ? yc[goff[j]] : 0.f;
            }
        }
    }
    __syncthreads();

    #pragma unroll
    for (int q = 0; q < 4; q++) {
        float* cur = (q & 1) ? ybuf1 : ybuf0;
        float* nxt = (q & 1) ? ybuf0 : ybuf1;
        // issue next chunk's loads first (overlap with compute below)
        if (q < 3) {
            const int chb = (q + 1) * YCH;
            for (int c2 = wid; c2 < YCH; c2 += 16) {
                const float* yc = g_y + xb + (long long)(chb + c2) * HWn;
                float* dst = nxt + c2 * YPOS;
                #pragma unroll
                for (int j = 0; j < 6; j++) {
                    int pos = lane + 32 * j;
                    if (pos < YPOS) dst[pos] = (goff[j] >= 0) ? yc[goff[j]] : 0.f;
                }
            }
        }
        // compute chunk q: 8 ch-groups x 128 px / 512 threads = 2 iters
        {
            const int p = tid & 127;
            const int py = p >> 4, pxx = p & 15;
            #pragma unroll
            for (int it = 0; it < 2; it++) {
                const int grp = (tid >> 7) + it * 4;       // 0..7, warp-uniform
                const int chl0 = grp * 4;
                const int ch0 = q * YCH + chl0;
                uint32_t hv[2], lv[2];
                #pragma unroll
                for (int j = 0; j < 4; j++) {
                    const int ch = ch0 + j;
                    const float* bp = cur + (chl0 + j) * YPOS + py * R3W + pxx;
                    float a = c_ldwb[ch];
                    #pragma unroll
                    for (int k = 0; k < 9; k++)
                        a = fmaf(c_ldww[ch][k], bp[(k/3)*R3W + (k%3)], a);
                    float v = gelu_exact(a);
                    unsigned short hb, lb;
                    bf16_split(v, hb, lb);
                    if (j & 1) { hv[j >> 1] |= (uint32_t)hb << 16; lv[j >> 1] |= (uint32_t)lb << 16; }
                    else       { hv[j >> 1]  = hb;                 lv[j >> 1]  = lb; }
                }
                *(uint2*)(smc + SM3_AH + p * (AS3*2) + ch0 * 2) = make_uint2(hv[0], hv[1]);
                *(uint2*)(smc + SM3_AL + p * (AS3*2) + ch0 * 2) = make_uint2(lv[0], lv[1]);
            }
        }
        __syncthreads();
    }

    // warp GEMM: 3 passes (AhBh, AhBl, AlBh) accumulated in fp32 fragments
    const int mi = wid >> 2, ni = wid & 3;
    const int lr = lane >> 2, lc = lane & 3;
    float cfr[8][4];
    #pragma unroll
    for (int t = 0; t < 8; t++) { cfr[t][0]=0.f; cfr[t][1]=0.f; cfr[t][2]=0.f; cfr[t][3]=0.f; }

    #pragma unroll
    for (int pass = 0; pass < 3; pass++) {
        const char* Ab = smc + (pass == 2 ? SM3_AL : SM3_AH);
        const char* Bb = smc + (pass == 1 ? SM3_BL : SM3_BH);
        #pragma unroll
        for (int k0 = 0; k0 < 8; k0++) {
            const int kb = k0 * 16;
            uint32_t a[2][4], bfr[4][2];
            #pragma unroll
            for (int m2 = 0; m2 < 2; m2++) {
                const char* ap = Ab + (mi*32 + m2*16 + lr) * (AS3*2) + (kb + lc*2) * 2;
                a[m2][0] = *(const uint32_t*)(ap);
                a[m2][1] = *(const uint32_t*)(ap + 8 * (AS3*2));
                a[m2][2] = *(const uint32_t*)(ap + 16);
                a[m2][3] = *(const uint32_t*)(ap + 8 * (AS3*2) + 16);
            }
            #pragma unroll
            for (int n4 = 0; n4 < 4; n4++) {
                const char* bp = Bb + (ni*32 + n4*8 + lr) * (AS3*2) + (kb + lc*2) * 2;
                bfr[n4][0] = *(const uint32_t*)(bp);
                bfr[n4][1] = *(const uint32_t*)(bp + 16);
            }
            #pragma unroll
            for (int m2 = 0; m2 < 2; m2++)
                #pragma unroll
                for (int n4 = 0; n4 < 4; n4++)
                    mma16816(cfr[m2*4 + n4], a[m2], bfr[n4]);
        }
    }

    // epilogue: add bias, store direct to gmem
    #pragma unroll
    for (int m2 = 0; m2 < 2; m2++) {
        #pragma unroll
        for (int n4 = 0; n4 < 4; n4++) {
            const float* cf = cfr[m2*4 + n4];
            const int p0 = mi*32 + m2*16 + lr;
            const int p1 = p0 + 8;
            const int oo = ni*32 + n4*8 + lc*2;
            const float b0v = bias[oo], b1v = bias[oo + 1];
            const long long r0 = xb + (long long)(h0 + (p0 >> 4)) * Wn + (w0 + (p0 & 15));
            const long long r1 = xb + (long long)(h0 + (p1 >> 4)) * Wn + (w0 + (p1 & 15));
            out[r0 + (long long)oo * HWn]       = cf[0] + b0v;
            out[r0 + (long long)(oo+1) * HWn]   = cf[1] + b1v;
            out[r1 + (long long)oo * HWn]       = cf[2] + b0v;
            out[r1 + (long long)(oo+1) * HWn]   = cf[3] + b1v;
        }
    }
}

// ================= launch =================
extern "C" void kernel_launch(void* const* d_in, const int* in_sizes, int n_in,
                              void* d_out, int out_size)
{
    (void)out_size;
    int idx_x = 0, idx_lpw = -1, idx_c5w = -1, idx_ldww = -1;
    int dw_w[4] = {-1,-1,-1,-1}, pw_w[4] = {-1,-1,-1,-1};
    int ndw = 0, npw = 0;
    for (int i = 0; i < n_in; i++) {
        int s = in_sizes[i];
        if (s > 100000)      idx_x = i;
        else if (s == 16384) idx_lpw = i;
        else if (s == 1152)  { if (idx_c5w < 0) idx_c5w = i; else idx_ldww = i; }
        else if (s == 288 && ndw < 4)  dw_w[ndw++] = i;
        else if (s == 1024 && npw < 4) pw_w[npw++] = i;
    }
    const int idx_c5b  = idx_c5w  + 1;
    const int idx_ldwb = idx_ldww + 1;
    const int idx_lpwb = idx_lpw  + 1;
    int v128[8]; int nv = 0;
    for (int i = 0; i < n_in; i++)
        if (in_sizes[i] == 128 && i != idx_c5b && i != idx_ldwb && i != idx_lpwb && nv < 8)
            v128[nv++] = i;
    const int idx_n1w = v128[0], idx_n1b = v128[1];
    const int idx_n2w = v128[2], idx_n2b = v128[3];

    const float* x = (const float*)d_in[idx_x];

    cudaMemcpyToSymbolAsync(c_n1w, d_in[idx_n1w], Cn*4, 0, cudaMemcpyDeviceToDevice);
    cudaMemcpyToSymbolAsync(c_n1b, d_in[idx_n1b], Cn*4, 0, cudaMemcpyDeviceToDevice);
    const int GS[4] = {1, 3, 0, 2};
    for (int g = 0; g < 4; g++) {
        int sbx = GS[g];
        cudaMemcpyToSymbolAsync(c_sdw_w,  d_in[dw_w[sbx]],     32*9*4,  g*32*9*4,  cudaMemcpyDeviceToDevice);
        cudaMemcpyToSymbolAsync(c_sdw_b,  d_in[dw_w[sbx] + 1], 32*4,    g*32*4,    cudaMemcpyDeviceToDevice);
        cudaMemcpyToSymbolAsync(g_spw_w,  d_in[pw_w[sbx]],     32*32*4, g*32*32*4, cudaMemcpyDeviceToDevice);
        cudaMemcpyToSymbolAsync(g_spw_b,  d_in[pw_w[sbx] + 1], 32*4,    g*32*4,    cudaMemcpyDeviceToDevice);
    }
    cudaMemcpyToSymbolAsync(g_c5w,  d_in[idx_c5w],  Cn*9*4, 0, cudaMemcpyDeviceToDevice);
    cudaMemcpyToSymbolAsync(g_c5b,  d_in[idx_c5b],  Cn*4,   0, cudaMemcpyDeviceToDevice);
    cudaMemcpyToSymbolAsync(g_n2w,  d_in[idx_n2w],  Cn*4,   0, cudaMemcpyDeviceToDevice);
    cudaMemcpyToSymbolAsync(g_n2b,  d_in[idx_n2b],  Cn*4,   0, cudaMemcpyDeviceToDevice);
    cudaMemcpyToSymbolAsync(c_ldww, d_in[idx_ldww], Cn*9*4, 0, cudaMemcpyDeviceToDevice);
    cudaMemcpyToSymbolAsync(c_ldwb, d_in[idx_ldwb], Cn*4,   0, cudaMemcpyDeviceToDevice);
    cudaMemcpyToSymbolAsync(c_lpwb, d_in[idx_lpwb], Cn*4,   0, cudaMemcpyDeviceToDevice);

    const int smem2 = SMEM2_FLOATS * 4;
    cudaFuncSetAttribute(k2_mix,   cudaFuncAttributeMaxDynamicSharedMemorySize, smem2);
    cudaFuncSetAttribute(k3_final, cudaFuncAttributeMaxDynamicSharedMemorySize, SM3_TOTAL);

    k0_prep<<<64, 256>>>((const float*)d_in[idx_lpw]);
    k1_stats<<<NPIX/256, 256>>>(x);
    k2_mix<<<dim3(Wn/T2W, Hn/T2H, Bn), NT2, smem2>>>(x);
    k3_final<<<dim3(Wn/T3W, Hn/T3H, Bn), NT3, SM3_TOTAL>>>((float*)d_out);
}